// round 12
// baseline (speedup 1.0000x reference)
#include <cuda_runtime.h>
#include <cuda_fp16.h>
#include <math.h>
#include <stdint.h>

#define BATCH 4
#define SEQ   2048
#define DM    1024
#define DFF   2752
#define DFP   2816
#define NH    16
#define DK    64
#define MROWS (BATCH*SEQ)

// ================= scratch =================
__device__ float g_h1 [(size_t)MROWS*DM];
__device__ float g_xn [(size_t)MROWS*DM];    // qhb+khb (fp16) during attention
__device__ float g_h  [(size_t)MROWS*DFP];   // vhb (fp16), then hb fp32
__device__ float g_g  [(size_t)MROWS*DFP];   // silu-product fp16 arena
__device__ float g_rt [SEQ*32*2];
__device__ __half g_ah[(size_t)MROWS*DFP];   // fp16 activation (GEMM A operand)
#define NWELEM 12845056
__device__ __half g_wh[(size_t)NWELEM];
#define OQKV 0
#define OO   3145728
#define OW1  4194304
#define OW3  7077888
#define OW2  9961472

// ================= PTX helpers =================
__device__ __forceinline__ uint32_t smem_u32(const void* p) {
    uint32_t a;
    asm("{ .reg .u64 t; cvta.to.shared.u64 t, %1; cvt.u32.u64 %0, t; }" : "=r"(a) : "l"(p));
    return a;
}
__device__ __forceinline__ void cpa16(uint32_t s, const void* g) {
    asm volatile("cp.async.cg.shared.global [%0], [%1], 16;" :: "r"(s), "l"(g));
}
#define CP_COMMIT() asm volatile("cp.async.commit_group;" ::: "memory")
#define CP_WAIT1()  asm volatile("cp.async.wait_group 1;" ::: "memory")
#define CP_WAIT0()  asm volatile("cp.async.wait_group 0;" ::: "memory")

__device__ __forceinline__ void ldm_x4(uint32_t* r, uint32_t a) {
    asm volatile("ldmatrix.sync.aligned.m8n8.x4.shared.b16 {%0,%1,%2,%3}, [%4];"
                 : "=r"(r[0]), "=r"(r[1]), "=r"(r[2]), "=r"(r[3]) : "r"(a));
}
__device__ __forceinline__ void ldm_x2(uint32_t* r, uint32_t a) {
    asm volatile("ldmatrix.sync.aligned.m8n8.x2.shared.b16 {%0,%1}, [%2];"
                 : "=r"(r[0]), "=r"(r[1]) : "r"(a));
}
__device__ __forceinline__ void ldm_x2t(uint32_t* r, uint32_t a) {
    asm volatile("ldmatrix.sync.aligned.m8n8.x2.trans.shared.b16 {%0,%1}, [%2];"
                 : "=r"(r[0]), "=r"(r[1]) : "r"(a));
}
// fp16 inputs, fp32 accumulate
#define MMAH(d, a, b) \
    asm volatile("mma.sync.aligned.m16n8k16.row.col.f32.f16.f16.f32 " \
        "{%0,%1,%2,%3}, {%4,%5,%6,%7}, {%8,%9}, {%0,%1,%2,%3};" \
        : "+f"((d)[0]), "+f"((d)[1]), "+f"((d)[2]), "+f"((d)[3]) \
        : "r"((a)[0]), "r"((a)[1]), "r"((a)[2]), "r"((a)[3]), "r"((b)[0]), "r"((b)[1]))

__device__ __forceinline__ uint32_t packh(float a, float b) {
    __half2 t = __floats2half2_rn(a, b);
    return *(uint32_t*)&t;
}

// ================= rope table =================
__global__ __launch_bounds__(256) void ropetab_k(float* __restrict__ rt)
{
    int idx = blockIdx.x * 256 + threadIdx.x;
    if (idx >= SEQ * 32) return;
    int s = idx >> 5, p = idx & 31;
    double inv = exp(-(double)(2 * p) * (9.210340371976184 / 64.0));
    double sd, cd;
    sincos((double)s * inv, &sd, &cd);
    rt[idx * 2]     = (float)cd;
    rt[idx * 2 + 1] = (float)sd;
}

// ================= weight convert fp32 -> fp16 (zero-padded) =================
__global__ __launch_bounds__(256) void conv_pad_k(const float* __restrict__ src,
                                                  __half* __restrict__ dst,
                                                  int srows, int scols,
                                                  int drows, int dcols)
{
    int i = blockIdx.x * 256 + threadIdx.x;
    int n4 = drows * (dcols >> 2);
    if (i >= n4) return;
    int r  = i / (dcols >> 2);
    int c4 = (i - r * (dcols >> 2)) << 2;
    float4 v = make_float4(0.f, 0.f, 0.f, 0.f);
    if (r < srows && c4 < scols)
        v = *(const float4*)(src + (size_t)r * scols + c4);
    size_t o = (size_t)r * dcols + c4;
    ((__half2*)(dst + o))[0] = __floats2half2_rn(v.x, v.y);
    ((__half2*)(dst + o))[1] = __floats2half2_rn(v.z, v.w);
}

// ================= RMSNorm -> fp16 =================
__global__ __launch_bounds__(256) void rmsnorm_h_k(const float* __restrict__ x,
                                                   const float* __restrict__ gain,
                                                   __half* __restrict__ outh)
{
    int row = blockIdx.x;
    const float4* xr = (const float4*)(x + (size_t)row * DM);
    float4 v = xr[threadIdx.x];
    float ss = v.x*v.x + v.y*v.y + v.z*v.z + v.w*v.w;
    #pragma unroll
    for (int o = 16; o; o >>= 1) ss += __shfl_xor_sync(0xffffffffu, ss, o);
    __shared__ float red[8];
    __shared__ float rinv;
    if ((threadIdx.x & 31) == 0) red[threadIdx.x >> 5] = ss;
    __syncthreads();
    if (threadIdx.x == 0) {
        float t = 0.f;
        #pragma unroll
        for (int i = 0; i < 8; i++) t += red[i];
        rinv = rsqrtf(t * (1.0f / DM) + 1e-5f);
    }
    __syncthreads();
    float r = rinv;
    float4 g = ((const float4*)gain)[threadIdx.x];
    size_t base = (size_t)row * (DM/2) + threadIdx.x * 2;
    ((__half2*)outh)[base]   = __floats2half2_rn(v.x*g.x*r, v.y*g.y*r);
    ((__half2*)outh)[base+1] = __floats2half2_rn(v.z*g.z*r, v.w*g.w*r);
}

// ======== fp16 HMMA GEMM core: 256x128x32 CTA tile, 512 thr, 16 warps 4x4 ========
#define GBK 32
#define LDT 40
#define TBUFA (256*LDT)           /* halves: A tile 256 x 32 padded */
#define TBUFB (128*LDT)           /* halves: B tile 128 x 32 padded */
#define SMEMB ((2*TBUFA + 2*TBUFB) * 2)   /* 61440 B */

#define GLOAD_STAGE(s, buf)                                                    \
    do {                                                                       \
        int k0_ = (s) * GBK;                                                   \
        _Pragma("unroll")                                                      \
        for (int i_ = 0; i_ < 2; i_++) {                                       \
            int r_ = row + i_ * 128;                                           \
            size_t ga_ = (size_t)(bm + r_) * K + k0_ + kc;                     \
            uint32_t sa_ = smb + (uint32_t)((buf)*TBUFA + r_*LDT + kc)*2;      \
            cpa16(sa_, Ah + ga_);                                              \
        }                                                                      \
        {                                                                      \
            size_t gb_ = (size_t)(bn + row) * K + k0_ + kc;                    \
            uint32_t sb_ = smb + (uint32_t)(2*TBUFA + (buf)*TBUFB + row*LDT + kc)*2; \
            cpa16(sb_, Bh + gb_);                                              \
        }                                                                      \
        CP_COMMIT();                                                           \
    } while (0)

#define GEMM_MAIN()                                                            \
    float acc[4][4][4];                                                        \
    _Pragma("unroll")                                                          \
    for (int a_ = 0; a_ < 4; a_++)                                             \
        _Pragma("unroll")                                                      \
        for (int b_ = 0; b_ < 4; b_++)                                         \
            _Pragma("unroll")                                                  \
            for (int c_ = 0; c_ < 4; c_++) acc[a_][b_][c_] = 0.f;              \
    const int row = tid >> 2;                                                  \
    const int kc  = (tid & 3) << 3;                                            \
    const int NS = K / GBK;                                                    \
    GLOAD_STAGE(0, 0);                                                         \
    GLOAD_STAGE(1, 1);                                                         \
    const int arow = lane & 15;                                                \
    const int acolo = ((lane >> 4) << 3);                                      \
    const int bro  = lane & 7;                                                 \
    const int bcolo = (((lane >> 3) & 1) << 3);                                \
    for (int s = 0; s < NS; s++) {                                             \
        const int buf = s & 1;                                                 \
        CP_WAIT1();                                                            \
        __syncthreads();                                                       \
        const uint32_t aoff = smb + (uint32_t)(buf*TBUFA)*2;                   \
        const uint32_t boff = smb + (uint32_t)(2*TBUFA + buf*TBUFB)*2;         \
        _Pragma("unroll")                                                      \
        for (int ks = 0; ks < 2; ks++) {                                       \
            const int k0 = ks * 16;                                            \
            uint32_t aH[4][4], bH[4][2];                                       \
            _Pragma("unroll")                                                  \
            for (int mt = 0; mt < 4; mt++) {                                   \
                int r = wm * 64 + mt * 16 + arow;                              \
                ldm_x4(aH[mt], aoff + (uint32_t)(r * LDT + k0 + acolo) * 2);   \
            }                                                                  \
            _Pragma("unroll")                                                  \
            for (int nt = 0; nt < 4; nt++) {                                   \
                int n = wn * 32 + nt * 8 + bro;                                \
                ldm_x2(bH[nt], boff + (uint32_t)(n * LDT + k0 + bcolo) * 2);   \
            }                                                                  \
            _Pragma("unroll")                                                  \
            for (int mt = 0; mt < 4; mt++)                                     \
                _Pragma("unroll")                                              \
                for (int nt = 0; nt < 4; nt++)                                 \
                    MMAH(acc[mt][nt], aH[mt], bH[nt]);                         \
        }                                                                      \
        __syncthreads();                                                       \
        if (s + 2 < NS) GLOAD_STAGE(s + 2, buf);                               \
    }

#define GEMM_PREAMBLE()                                                        \
    extern __shared__ __align__(128) __half sm[];                              \
    const uint32_t smb = smem_u32(sm);                                         \
    const int tid  = threadIdx.x;                                              \
    const int lane = tid & 31;                                                 \
    const int wid  = tid >> 5;                                                 \
    const int wm   = wid >> 2;                                                 \
    const int wn   = wid & 3;                                                  \
    const int bm   = blockIdx.y * 256;                                         \
    const int bn   = blockIdx.x * 128;

__global__ __launch_bounds__(512, 1) void gemmh_k(
    const __half* __restrict__ Ah, const __half* __restrict__ Bh,
    float* __restrict__ C, const float* __restrict__ res, int N, int K)
{
    GEMM_PREAMBLE();
    GEMM_MAIN();

    const int gid = lane >> 2, t4 = lane & 3;
    #pragma unroll
    for (int mt = 0; mt < 4; mt++) {
        int r0 = bm + wm * 64 + mt * 16 + gid;
        #pragma unroll
        for (int nt = 0; nt < 4; nt++) {
            int col = bn + wn * 32 + nt * 8 + t4 * 2;
            size_t o0 = (size_t)r0 * N + col;
            size_t o1 = o0 + (size_t)8 * N;
            float2 v0 = make_float2(acc[mt][nt][0], acc[mt][nt][1]);
            float2 v1 = make_float2(acc[mt][nt][2], acc[mt][nt][3]);
            if (res) {
                float2 r0v = *(const float2*)(res + o0);
                float2 r1v = *(const float2*)(res + o1);
                v0.x += r0v.x; v0.y += r0v.y;
                v1.x += r1v.x; v1.y += r1v.y;
            }
            *(float2*)(C + o0) = v0;
            *(float2*)(C + o1) = v1;
        }
    }
}

// ======== w3 GEMM with fused SiLU: out = silu(hb) * acc, fp16 ========
__global__ __launch_bounds__(512, 1) void gemmw3silu_k(
    const __half* __restrict__ Ah, const __half* __restrict__ Bh,
    const float* __restrict__ hb, __half* __restrict__ outh, int N, int K)
{
    GEMM_PREAMBLE();
    GEMM_MAIN();

    const int gid = lane >> 2, t4 = lane & 3;
    #pragma unroll
    for (int mt = 0; mt < 4; mt++) {
        int r0 = bm + wm * 64 + mt * 16 + gid;
        #pragma unroll
        for (int nt = 0; nt < 4; nt++) {
            int col = bn + wn * 32 + nt * 8 + t4 * 2;
            size_t o0 = (size_t)r0 * N + col;
            size_t o1 = o0 + (size_t)8 * N;
            float2 h0 = *(const float2*)(hb + o0);
            float2 h1 = *(const float2*)(hb + o1);
            float y0 = acc[mt][nt][0] * h0.x / (1.f + __expf(-h0.x));
            float y1 = acc[mt][nt][1] * h0.y / (1.f + __expf(-h0.y));
            float y2 = acc[mt][nt][2] * h1.x / (1.f + __expf(-h1.x));
            float y3 = acc[mt][nt][3] * h1.y / (1.f + __expf(-h1.y));
            *(__half2*)(outh + o0) = __floats2half2_rn(y0, y1);
            *(__half2*)(outh + o1) = __floats2half2_rn(y2, y3);
        }
    }
}

// ======== QKV GEMM with fused RoPE + head-major fp16 output ========
__global__ __launch_bounds__(512, 1) void gemmqkv_k(
    const __half* __restrict__ Ah, const __half* __restrict__ Bh,
    const float* __restrict__ rt,
    __half* __restrict__ qhb, __half* __restrict__ khb,
    __half* __restrict__ vhb)
{
    const int K = DM;
    GEMM_PREAMBLE();
    GEMM_MAIN();

    const int gid = lane >> 2, t4 = lane & 3;
    #pragma unroll
    for (int mt = 0; mt < 4; mt++) {
        int r0 = bm + wm * 64 + mt * 16 + gid;
        #pragma unroll
        for (int nt = 0; nt < 4; nt++) {
            int col = bn + wn * 32 + nt * 8 + t4 * 2;
            int t   = col >> 10;
            int rem = col & 1023;
            int hh  = rem >> 6;
            int d   = rem & 63;
            int p   = d >> 1;
            __half* dstbuf = (t == 0) ? qhb : (t == 1) ? khb : vhb;
            #pragma unroll
            for (int half_ = 0; half_ < 2; half_++) {
                int r = r0 + half_ * 8;
                float v0 = acc[mt][nt][half_ * 2];
                float v1 = acc[mt][nt][half_ * 2 + 1];
                int s = r & (SEQ - 1);
                int b = r >> 11;
                size_t dst = ((size_t)(b * NH + hh) * SEQ + s) * DK + d;
                if (t < 2) {
                    float2 cs = ((const float2*)rt)[s * 32 + p];
                    float x0 = cs.x * v0 - cs.y * v1;
                    float x1 = cs.y * v0 + cs.x * v1;
                    v0 = x0; v1 = x1;
                }
                *(__half2*)(dstbuf + dst) = __floats2half2_rn(v0, v1);
            }
        }
    }
}

// ================= fp16 HMMA flash attention =================
#define QT 64
#define LDS 72
#define NEG_BIG (-1.0e30f)

__global__ __launch_bounds__(128) void flashm_k(const __half* __restrict__ qhb,
                                                const __half* __restrict__ khb,
                                                const __half* __restrict__ vhb,
                                                __half* __restrict__ ah)
{
    __shared__ __align__(128) __half Qs[QT * LDS];
    __shared__ __align__(128) __half Ks[2][64 * LDS];
    __shared__ __align__(128) __half Vs[2][64 * LDS];

    const int tid  = threadIdx.x;
    const int lane = tid & 31;
    const int w    = tid >> 5;
    const int bh   = blockIdx.y;
    const int b    = bh >> 4, h = bh & 15;
    const int qt   = gridDim.x - 1 - blockIdx.x;
    const int qbase = qt * QT;

    const uint32_t qs = smem_u32(Qs);
    const uint32_t ks0 = smem_u32(Ks);
    const uint32_t vs0 = smem_u32(Vs);

    const __half* qg = qhb + ((size_t)bh * SEQ + qbase) * DK;
    #pragma unroll
    for (int i = 0; i < 4; i++) {
        int slot = tid + (i << 7);
        int r = slot >> 3, c8 = (slot & 7) << 3;
        cpa16(qs + (uint32_t)(r * LDS + c8) * 2, qg + r * 64 + c8);
    }
    CP_COMMIT();

    const __half* kg = khb + (size_t)bh * SEQ * DK;
    const __half* vg = vhb + (size_t)bh * SEQ * DK;

    #define FKV_LOAD(t, buf) do {                                              \
        int n0_ = (t) * 64;                                                    \
        _Pragma("unroll")                                                      \
        for (int i_ = 0; i_ < 4; i_++) {                                       \
            int slot_ = tid + (i_ << 7);                                       \
            int r_ = slot_ >> 3, c8_ = (slot_ & 7) << 3;                       \
            uint32_t so_ = (uint32_t)((buf) * 64 * LDS + r_ * LDS + c8_) * 2;  \
            cpa16(ks0 + so_, kg + (size_t)(n0_ + r_) * 64 + c8_);              \
            cpa16(vs0 + so_, vg + (size_t)(n0_ + r_) * 64 + c8_);              \
        }                                                                      \
        CP_COMMIT();                                                           \
    } while (0)

    const int T = qt + 1;
    FKV_LOAD(0, 0);

    const int gid = lane >> 2, t4 = lane & 3;
    const int qg0 = qbase + w * 16 + gid;

    uint32_t aQ[4][4];
    float oacc[8][4];
    #pragma unroll
    for (int i = 0; i < 8; i++)
        #pragma unroll
        for (int j = 0; j < 4; j++) oacc[i][j] = 0.f;
    float m0 = NEG_BIG, m1 = NEG_BIG, l0 = 0.f, l1 = 0.f;

    const int arow = lane & 15;
    const int acolo = (lane >> 4) << 3;
    const int bro = lane & 7;
    const int bcolo = ((lane >> 3) & 1) << 3;
    const int l15 = lane & 15;

    for (int t = 0; t < T; t++) {
        const int buf = t & 1;
        if (t + 1 < T) { FKV_LOAD(t + 1, buf ^ 1); CP_WAIT1(); }
        else           { CP_WAIT0(); }
        __syncthreads();

        if (t == 0) {
            #pragma unroll
            for (int k = 0; k < 4; k++) {
                uint32_t ad = qs + (uint32_t)((w * 16 + arow) * LDS + k * 16 + acolo) * 2;
                ldm_x4(aQ[k], ad);
            }
        }

        const uint32_t kb = ks0 + (uint32_t)(buf * 64 * LDS) * 2;
        const uint32_t vb = vs0 + (uint32_t)(buf * 64 * LDS) * 2;
        const int n0 = t * 64;

        float sacc[8][4];
        #pragma unroll
        for (int i = 0; i < 8; i++)
            #pragma unroll
            for (int j = 0; j < 4; j++) sacc[i][j] = 0.f;

        #pragma unroll
        for (int k = 0; k < 4; k++) {
            #pragma unroll
            for (int nt = 0; nt < 8; nt++) {
                uint32_t bk[2];
                uint32_t bd = kb + (uint32_t)((nt * 8 + bro) * LDS + k * 16 + bcolo) * 2;
                ldm_x2(bk, bd);
                MMAH(sacc[nt], aQ[k], bk);
            }
        }

        const bool diag = (t == qt);
        #pragma unroll
        for (int nt = 0; nt < 8; nt++) {
            int kvb = n0 + nt * 8 + t4 * 2;
            #pragma unroll
            for (int c = 0; c < 2; c++) {
                float s0 = sacc[nt][c]   * 0.125f;
                float s1 = sacc[nt][c+2] * 0.125f;
                if (diag) {
                    if (kvb + c > qg0)     s0 = NEG_BIG;
                    if (kvb + c > qg0 + 8) s1 = NEG_BIG;
                }
                sacc[nt][c]   = s0;
                sacc[nt][c+2] = s1;
            }
        }

        float vmax0 = NEG_BIG, vmax1 = NEG_BIG;
        #pragma unroll
        for (int nt = 0; nt < 8; nt++) {
            vmax0 = fmaxf(vmax0, fmaxf(sacc[nt][0], sacc[nt][1]));
            vmax1 = fmaxf(vmax1, fmaxf(sacc[nt][2], sacc[nt][3]));
        }
        vmax0 = fmaxf(vmax0, __shfl_xor_sync(0xffffffffu, vmax0, 1));
        vmax0 = fmaxf(vmax0, __shfl_xor_sync(0xffffffffu, vmax0, 2));
        vmax1 = fmaxf(vmax1, __shfl_xor_sync(0xffffffffu, vmax1, 1));
        vmax1 = fmaxf(vmax1, __shfl_xor_sync(0xffffffffu, vmax1, 2));

        float mn0 = fmaxf(m0, vmax0), mn1 = fmaxf(m1, vmax1);
        float corr0 = __expf(m0 - mn0), corr1 = __expf(m1 - mn1);
        m0 = mn0; m1 = mn1;

        float lsum0 = 0.f, lsum1 = 0.f;
        #pragma unroll
        for (int nt = 0; nt < 8; nt++) {
            float p0 = __expf(sacc[nt][0] - mn0);
            float p1 = __expf(sacc[nt][1] - mn0);
            float p2 = __expf(sacc[nt][2] - mn1);
            float p3 = __expf(sacc[nt][3] - mn1);
            sacc[nt][0] = p0; sacc[nt][1] = p1; sacc[nt][2] = p2; sacc[nt][3] = p3;
            lsum0 += p0 + p1; lsum1 += p2 + p3;
        }
        lsum0 += __shfl_xor_sync(0xffffffffu, lsum0, 1);
        lsum0 += __shfl_xor_sync(0xffffffffu, lsum0, 2);
        lsum1 += __shfl_xor_sync(0xffffffffu, lsum1, 1);
        lsum1 += __shfl_xor_sync(0xffffffffu, lsum1, 2);
        l0 = l0 * corr0 + lsum0;
        l1 = l1 * corr1 + lsum1;

        #pragma unroll
        for (int nt = 0; nt < 8; nt++) {
            oacc[nt][0] *= corr0; oacc[nt][1] *= corr0;
            oacc[nt][2] *= corr1; oacc[nt][3] *= corr1;
        }

        #pragma unroll
        for (int kp = 0; kp < 4; kp++) {
            uint32_t pa[4];
            pa[0] = packh(sacc[2*kp][0],   sacc[2*kp][1]);
            pa[1] = packh(sacc[2*kp][2],   sacc[2*kp][3]);
            pa[2] = packh(sacc[2*kp+1][0], sacc[2*kp+1][1]);
            pa[3] = packh(sacc[2*kp+1][2], sacc[2*kp+1][3]);
            #pragma unroll
            for (int ntd = 0; ntd < 8; ntd++) {
                uint32_t bv[2];
                uint32_t vd = vb + (uint32_t)((kp * 16 + l15) * LDS + ntd * 8) * 2;
                ldm_x2t(bv, vd);
                MMAH(oacc[ntd], pa, bv);
            }
        }
        __syncthreads();
    }

    float invl0 = 1.f / l0, invl1 = 1.f / l1;
    const size_t row0 = (size_t)(b * SEQ + qbase + w * 16 + gid);
    #pragma unroll
    for (int ntd = 0; ntd < 8; ntd++) {
        int col = h * 64 + ntd * 8 + t4 * 2;
        *(__half2*)(ah + row0 * DM + col) =
            __floats2half2_rn(oacc[ntd][0] * invl0, oacc[ntd][1] * invl0);
        *(__half2*)(ah + (row0 + 8) * DM + col) =
            __floats2half2_rn(oacc[ntd][2] * invl1, oacc[ntd][3] * invl1);
    }
}

// ================= launch =================
extern "C" void kernel_launch(void* const* d_in, const int* in_sizes, int n_in,
                              void* d_out, int out_size)
{
    const float* x      = (const float*)d_in[0];
    const float* qkv_w  = (const float*)d_in[2];
    const float* o_w    = (const float*)d_in[3];
    const float* gain1  = (const float*)d_in[4];
    const float* gain2  = (const float*)d_in[5];
    const float* w1     = (const float*)d_in[6];
    const float* w2     = (const float*)d_in[7];
    const float* w3     = (const float*)d_in[8];
    float* out = (float*)d_out;

    float *h1, *hb, *gb, *rt, *xn;
    __half *ah, *wh;
    cudaGetSymbolAddress((void**)&h1,  g_h1);
    cudaGetSymbolAddress((void**)&xn,  g_xn);
    cudaGetSymbolAddress((void**)&hb,  g_h);
    cudaGetSymbolAddress((void**)&gb,  g_g);
    cudaGetSymbolAddress((void**)&rt,  g_rt);
    cudaGetSymbolAddress((void**)&ah,  g_ah);
    cudaGetSymbolAddress((void**)&wh,  g_wh);

    __half* qhb = (__half*)xn;
    __half* khb = (__half*)xn + (size_t)MROWS*DM;
    __half* vhb = (__half*)hb;
    __half* sgh = (__half*)gb;      // silu-product fp16

    cudaFuncSetAttribute(gemmh_k,      cudaFuncAttributeMaxDynamicSharedMemorySize, SMEMB);
    cudaFuncSetAttribute(gemmqkv_k,    cudaFuncAttributeMaxDynamicSharedMemorySize, SMEMB);
    cudaFuncSetAttribute(gemmw3silu_k, cudaFuncAttributeMaxDynamicSharedMemorySize, SMEMB);

    ropetab_k<<<(SEQ*32 + 255)/256, 256>>>(rt);
    conv_pad_k<<<(3145728/4 + 255)/256, 256>>>(qkv_w, wh+OQKV, 3072,1024,3072,1024);
    rmsnorm_h_k<<<MROWS, 256>>>(x, gain1, ah);
    gemmqkv_k<<<dim3(3072/128, MROWS/256), 512, SMEMB>>>(ah, wh+OQKV, rt, qhb, khb, vhb);
    flashm_k<<<dim3(SEQ/QT, BATCH*NH), 128>>>(qhb, khb, vhb, ah);
    conv_pad_k<<<(1048576/4 + 255)/256, 256>>>(o_w, wh+OO, 1024,1024,1024,1024);
    gemmh_k<<<dim3(DM/128, MROWS/256), 512, SMEMB>>>(ah, wh+OO, h1, x, DM, DM);
    rmsnorm_h_k<<<MROWS, 256>>>(h1, gain2, ah);
    conv_pad_k<<<((DFP*1024)/4 + 255)/256, 256>>>(w1, wh+OW1, DFF,1024,DFP,1024);
    conv_pad_k<<<((DFP*1024)/4 + 255)/256, 256>>>(w3, wh+OW3, DFF,1024,DFP,1024);
    gemmh_k<<<dim3(DFP/128, MROWS/256), 512, SMEMB>>>(ah, wh+OW1, hb, nullptr, DFP, DM);
    gemmw3silu_k<<<dim3(DFP/128, MROWS/256), 512, SMEMB>>>(ah, wh+OW3, hb, sgh, DFP, DM);
    conv_pad_k<<<((1024*DFP)/4 + 255)/256, 256>>>(w2, wh+OW2, 1024,DFF,1024,DFP);
    gemmh_k<<<dim3(DM/128, MROWS/256), 512, SMEMB>>>(sgh, wh+OW2, out, h1, DM, DFP);
}

// round 13
// speedup vs baseline: 1.1220x; 1.1220x over previous
#include <cuda_runtime.h>
#include <cuda_fp16.h>
#include <math.h>
#include <stdint.h>

#define BATCH 4
#define SEQ   2048
#define DM    1024
#define DFF   2752
#define DFP   2816
#define NH    16
#define DK    64
#define MROWS (BATCH*SEQ)

// ================= scratch =================
__device__ float g_h1 [(size_t)MROWS*DM];
__device__ float g_xn [(size_t)MROWS*DM];    // qhb+khb (fp16) during attention
__device__ float g_h  [(size_t)MROWS*DFP];   // vhb (fp16), then hb fp32
__device__ float g_g  [(size_t)MROWS*DFP];   // silu-product fp16 arena
__device__ float g_rt [SEQ*32*2];
__device__ __half g_ah[(size_t)MROWS*DFP];   // fp16 activation (GEMM A operand)
#define NWELEM 12845056
__device__ __half g_wh[(size_t)NWELEM];
#define OQKV 0
#define OO   3145728
#define OW1  4194304
#define OW3  7077888
#define OW2  9961472

// ================= PTX helpers =================
__device__ __forceinline__ uint32_t smem_u32(const void* p) {
    uint32_t a;
    asm("{ .reg .u64 t; cvta.to.shared.u64 t, %1; cvt.u32.u64 %0, t; }" : "=r"(a) : "l"(p));
    return a;
}
__device__ __forceinline__ void cpa16(uint32_t s, const void* g) {
    asm volatile("cp.async.cg.shared.global [%0], [%1], 16;" :: "r"(s), "l"(g));
}
#define CP_COMMIT() asm volatile("cp.async.commit_group;" ::: "memory")
#define CP_WAIT1()  asm volatile("cp.async.wait_group 1;" ::: "memory")
#define CP_WAIT0()  asm volatile("cp.async.wait_group 0;" ::: "memory")

__device__ __forceinline__ void ldm_x4(uint32_t* r, uint32_t a) {
    asm volatile("ldmatrix.sync.aligned.m8n8.x4.shared.b16 {%0,%1,%2,%3}, [%4];"
                 : "=r"(r[0]), "=r"(r[1]), "=r"(r[2]), "=r"(r[3]) : "r"(a));
}
__device__ __forceinline__ void ldm_x2(uint32_t* r, uint32_t a) {
    asm volatile("ldmatrix.sync.aligned.m8n8.x2.shared.b16 {%0,%1}, [%2];"
                 : "=r"(r[0]), "=r"(r[1]) : "r"(a));
}
__device__ __forceinline__ void ldm_x2t(uint32_t* r, uint32_t a) {
    asm volatile("ldmatrix.sync.aligned.m8n8.x2.trans.shared.b16 {%0,%1}, [%2];"
                 : "=r"(r[0]), "=r"(r[1]) : "r"(a));
}
// fp16 inputs, fp32 accumulate
#define MMAH(d, a, b) \
    asm volatile("mma.sync.aligned.m16n8k16.row.col.f32.f16.f16.f32 " \
        "{%0,%1,%2,%3}, {%4,%5,%6,%7}, {%8,%9}, {%0,%1,%2,%3};" \
        : "+f"((d)[0]), "+f"((d)[1]), "+f"((d)[2]), "+f"((d)[3]) \
        : "r"((a)[0]), "r"((a)[1]), "r"((a)[2]), "r"((a)[3]), "r"((b)[0]), "r"((b)[1]))

__device__ __forceinline__ uint32_t packh(float a, float b) {
    __half2 t = __floats2half2_rn(a, b);
    return *(uint32_t*)&t;
}

// ================= rope table =================
__global__ __launch_bounds__(256) void ropetab_k(float* __restrict__ rt)
{
    int idx = blockIdx.x * 256 + threadIdx.x;
    if (idx >= SEQ * 32) return;
    int s = idx >> 5, p = idx & 31;
    double inv = exp(-(double)(2 * p) * (9.210340371976184 / 64.0));
    double sd, cd;
    sincos((double)s * inv, &sd, &cd);
    rt[idx * 2]     = (float)cd;
    rt[idx * 2 + 1] = (float)sd;
}

// ================= weight convert fp32 -> fp16 (zero-padded) =================
__global__ __launch_bounds__(256) void conv_pad_k(const float* __restrict__ src,
                                                  __half* __restrict__ dst,
                                                  int srows, int scols,
                                                  int drows, int dcols)
{
    int i = blockIdx.x * 256 + threadIdx.x;
    int n4 = drows * (dcols >> 2);
    if (i >= n4) return;
    int r  = i / (dcols >> 2);
    int c4 = (i - r * (dcols >> 2)) << 2;
    float4 v = make_float4(0.f, 0.f, 0.f, 0.f);
    if (r < srows && c4 < scols)
        v = *(const float4*)(src + (size_t)r * scols + c4);
    size_t o = (size_t)r * dcols + c4;
    ((__half2*)(dst + o))[0] = __floats2half2_rn(v.x, v.y);
    ((__half2*)(dst + o))[1] = __floats2half2_rn(v.z, v.w);
}

// ================= RMSNorm -> fp16 =================
__global__ __launch_bounds__(256) void rmsnorm_h_k(const float* __restrict__ x,
                                                   const float* __restrict__ gain,
                                                   __half* __restrict__ outh)
{
    int row = blockIdx.x;
    const float4* xr = (const float4*)(x + (size_t)row * DM);
    float4 v = xr[threadIdx.x];
    float ss = v.x*v.x + v.y*v.y + v.z*v.z + v.w*v.w;
    #pragma unroll
    for (int o = 16; o; o >>= 1) ss += __shfl_xor_sync(0xffffffffu, ss, o);
    __shared__ float red[8];
    __shared__ float rinv;
    if ((threadIdx.x & 31) == 0) red[threadIdx.x >> 5] = ss;
    __syncthreads();
    if (threadIdx.x == 0) {
        float t = 0.f;
        #pragma unroll
        for (int i = 0; i < 8; i++) t += red[i];
        rinv = rsqrtf(t * (1.0f / DM) + 1e-5f);
    }
    __syncthreads();
    float r = rinv;
    float4 g = ((const float4*)gain)[threadIdx.x];
    size_t base = (size_t)row * (DM/2) + threadIdx.x * 2;
    ((__half2*)outh)[base]   = __floats2half2_rn(v.x*g.x*r, v.y*g.y*r);
    ((__half2*)outh)[base+1] = __floats2half2_rn(v.z*g.z*r, v.w*g.w*r);
}

// ======== fp16 HMMA GEMM core (128x128x32, 256 thr, 2 CTAs/SM) ========
#define GBK 32
#define LDT 40
#define TBUF (128*LDT)            /* halves per tile (10240 B) */
#define SMEMB (4 * TBUF * 2)      /* 40960 B: 2 bufs x (A + B) */

#define GLOAD_STAGE(s, buf)                                                    \
    do {                                                                       \
        int k0_ = (s) * GBK;                                                   \
        _Pragma("unroll")                                                      \
        for (int i_ = 0; i_ < 2; i_++) {                                       \
            int r_ = row + i_ * 64;                                            \
            size_t ga_ = (size_t)(bm + r_) * K + k0_ + kc;                     \
            size_t gb_ = (size_t)(bn + r_) * K + k0_ + kc;                     \
            uint32_t sa_ = smb + (uint32_t)(((buf))*TBUF + r_*LDT + kc)*2;     \
            uint32_t sb_ = smb + (uint32_t)((2+(buf))*TBUF + r_*LDT + kc)*2;   \
            cpa16(sa_, Ah + ga_);                                              \
            cpa16(sb_, Bh + gb_);                                              \
        }                                                                      \
        CP_COMMIT();                                                           \
    } while (0)

#define GEMM_MAIN()                                                            \
    float acc[4][4][4];                                                        \
    _Pragma("unroll")                                                          \
    for (int a_ = 0; a_ < 4; a_++)                                             \
        _Pragma("unroll")                                                      \
        for (int b_ = 0; b_ < 4; b_++)                                         \
            _Pragma("unroll")                                                  \
            for (int c_ = 0; c_ < 4; c_++) acc[a_][b_][c_] = 0.f;              \
    const int row = tid >> 2;                                                  \
    const int kc  = (tid & 3) << 3;                                            \
    const int NS = K / GBK;                                                    \
    GLOAD_STAGE(0, 0);                                                         \
    GLOAD_STAGE(1, 1);                                                         \
    const int arow = lane & 15;                                                \
    const int acolo = ((lane >> 4) << 3);                                      \
    const int bro  = lane & 7;                                                 \
    const int bcolo = (((lane >> 3) & 1) << 3);                                \
    for (int s = 0; s < NS; s++) {                                             \
        const int buf = s & 1;                                                 \
        CP_WAIT1();                                                            \
        __syncthreads();                                                       \
        const uint32_t aoff = smb + (uint32_t)(buf*TBUF)*2;                    \
        const uint32_t boff = smb + (uint32_t)((2 + buf)*TBUF)*2;              \
        _Pragma("unroll")                                                      \
        for (int ks = 0; ks < 2; ks++) {                                       \
            const int k0 = ks * 16;                                            \
            uint32_t aH[4][4], bH[4][2];                                       \
            _Pragma("unroll")                                                  \
            for (int mt = 0; mt < 4; mt++) {                                   \
                int r = wm * 64 + mt * 16 + arow;                              \
                ldm_x4(aH[mt], aoff + (uint32_t)(r * LDT + k0 + acolo) * 2);   \
            }                                                                  \
            _Pragma("unroll")                                                  \
            for (int nt = 0; nt < 4; nt++) {                                   \
                int n = wn * 32 + nt * 8 + bro;                                \
                ldm_x2(bH[nt], boff + (uint32_t)(n * LDT + k0 + bcolo) * 2);   \
            }                                                                  \
            _Pragma("unroll")                                                  \
            for (int mt = 0; mt < 4; mt++)                                     \
                _Pragma("unroll")                                              \
                for (int nt = 0; nt < 4; nt++)                                 \
                    MMAH(acc[mt][nt], aH[mt], bH[nt]);                         \
        }                                                                      \
        __syncthreads();                                                       \
        if (s + 2 < NS) GLOAD_STAGE(s + 2, buf);                               \
    }

#define GEMM_PREAMBLE()                                                        \
    extern __shared__ __align__(128) __half sm[];                              \
    const uint32_t smb = smem_u32(sm);                                         \
    const int tid  = threadIdx.x;                                              \
    const int lane = tid & 31;                                                 \
    const int wid  = tid >> 5;                                                 \
    const int wm   = wid >> 2;                                                 \
    const int wn   = wid & 3;                                                  \
    const int bm   = blockIdx.y * 128;                                         \
    const int bn   = blockIdx.x * 128;

__global__ __launch_bounds__(256, 2) void gemmh_k(
    const __half* __restrict__ Ah, const __half* __restrict__ Bh,
    float* __restrict__ C, const float* __restrict__ res, int N, int K)
{
    GEMM_PREAMBLE();
    GEMM_MAIN();

    const int gid = lane >> 2, t4 = lane & 3;
    #pragma unroll
    for (int mt = 0; mt < 4; mt++) {
        int r0 = bm + wm * 64 + mt * 16 + gid;
        #pragma unroll
        for (int nt = 0; nt < 4; nt++) {
            int col = bn + wn * 32 + nt * 8 + t4 * 2;
            size_t o0 = (size_t)r0 * N + col;
            size_t o1 = o0 + (size_t)8 * N;
            float2 v0 = make_float2(acc[mt][nt][0], acc[mt][nt][1]);
            float2 v1 = make_float2(acc[mt][nt][2], acc[mt][nt][3]);
            if (res) {
                float2 r0v = *(const float2*)(res + o0);
                float2 r1v = *(const float2*)(res + o1);
                v0.x += r0v.x; v0.y += r0v.y;
                v1.x += r1v.x; v1.y += r1v.y;
            }
            *(float2*)(C + o0) = v0;
            *(float2*)(C + o1) = v1;
        }
    }
}

// ======== w3 GEMM with fused SiLU: out = silu(hb) * acc, fp16 ========
__global__ __launch_bounds__(256, 2) void gemmw3silu_k(
    const __half* __restrict__ Ah, const __half* __restrict__ Bh,
    const float* __restrict__ hb, __half* __restrict__ outh, int N, int K)
{
    GEMM_PREAMBLE();
    GEMM_MAIN();

    const int gid = lane >> 2, t4 = lane & 3;
    #pragma unroll
    for (int mt = 0; mt < 4; mt++) {
        int r0 = bm + wm * 64 + mt * 16 + gid;
        #pragma unroll
        for (int nt = 0; nt < 4; nt++) {
            int col = bn + wn * 32 + nt * 8 + t4 * 2;
            size_t o0 = (size_t)r0 * N + col;
            size_t o1 = o0 + (size_t)8 * N;
            float2 h0 = *(const float2*)(hb + o0);
            float2 h1 = *(const float2*)(hb + o1);
            float y0 = acc[mt][nt][0] * h0.x / (1.f + __expf(-h0.x));
            float y1 = acc[mt][nt][1] * h0.y / (1.f + __expf(-h0.y));
            float y2 = acc[mt][nt][2] * h1.x / (1.f + __expf(-h1.x));
            float y3 = acc[mt][nt][3] * h1.y / (1.f + __expf(-h1.y));
            *(__half2*)(outh + o0) = __floats2half2_rn(y0, y1);
            *(__half2*)(outh + o1) = __floats2half2_rn(y2, y3);
        }
    }
}

// ======== QKV GEMM with fused RoPE + head-major fp16 output ========
__global__ __launch_bounds__(256, 2) void gemmqkv_k(
    const __half* __restrict__ Ah, const __half* __restrict__ Bh,
    const float* __restrict__ rt,
    __half* __restrict__ qhb, __half* __restrict__ khb,
    __half* __restrict__ vhb)
{
    const int K = DM;
    GEMM_PREAMBLE();
    GEMM_MAIN();

    const int gid = lane >> 2, t4 = lane & 3;
    #pragma unroll
    for (int mt = 0; mt < 4; mt++) {
        int r0 = bm + wm * 64 + mt * 16 + gid;
        #pragma unroll
        for (int nt = 0; nt < 4; nt++) {
            int col = bn + wn * 32 + nt * 8 + t4 * 2;
            int t   = col >> 10;
            int rem = col & 1023;
            int hh  = rem >> 6;
            int d   = rem & 63;
            int p   = d >> 1;
            __half* dstbuf = (t == 0) ? qhb : (t == 1) ? khb : vhb;
            #pragma unroll
            for (int half_ = 0; half_ < 2; half_++) {
                int r = r0 + half_ * 8;
                float v0 = acc[mt][nt][half_ * 2];
                float v1 = acc[mt][nt][half_ * 2 + 1];
                int s = r & (SEQ - 1);
                int b = r >> 11;
                size_t dst = ((size_t)(b * NH + hh) * SEQ + s) * DK + d;
                if (t < 2) {
                    float2 cs = ((const float2*)rt)[s * 32 + p];
                    float x0 = cs.x * v0 - cs.y * v1;
                    float x1 = cs.y * v0 + cs.x * v1;
                    v0 = x0; v1 = x1;
                }
                *(__half2*)(dstbuf + dst) = __floats2half2_rn(v0, v1);
            }
        }
    }
}

// ================= fp16 HMMA flash attention, QT=128, 256 threads =================
#define QT 128
#define LDS 72
#define NEG_BIG (-1.0e30f)
// dynamic smem layout (halves): Q[QT*LDS] | K[2][64*LDS] | V[2][64*LDS]
#define FQ_OFF  0
#define FK_OFF  (QT*LDS)
#define FV_OFF  (QT*LDS + 2*64*LDS)
#define FSMEM   ((QT*LDS + 4*64*LDS) * 2)   /* 55296 B */

__global__ __launch_bounds__(256) void flashm_k(const __half* __restrict__ qhb,
                                                const __half* __restrict__ khb,
                                                const __half* __restrict__ vhb,
                                                __half* __restrict__ ah)
{
    extern __shared__ __align__(128) __half fsm[];
    const uint32_t qs  = smem_u32(fsm) + FQ_OFF * 2;
    const uint32_t ks0 = smem_u32(fsm) + FK_OFF * 2;
    const uint32_t vs0 = smem_u32(fsm) + FV_OFF * 2;

    const int tid  = threadIdx.x;
    const int lane = tid & 31;
    const int w    = tid >> 5;               // 0..7, 16 q-rows each
    const int bh   = blockIdx.y;
    const int b    = bh >> 4, h = bh & 15;
    const int qt   = gridDim.x - 1 - blockIdx.x;   // heavy blocks first
    const int qbase = qt * QT;

    // load Q tile (128 x 64)
    const __half* qg = qhb + ((size_t)bh * SEQ + qbase) * DK;
    #pragma unroll
    for (int i = 0; i < 4; i++) {
        int slot = tid + (i << 8);           // 0..1023
        int r = slot >> 3, c8 = (slot & 7) << 3;
        cpa16(qs + (uint32_t)(r * LDS + c8) * 2, qg + r * 64 + c8);
    }
    CP_COMMIT();

    const __half* kg = khb + (size_t)bh * SEQ * DK;
    const __half* vg = vhb + (size_t)bh * SEQ * DK;

    #define FKV_LOAD(t, buf) do {                                              \
        int n0_ = (t) * 64;                                                    \
        _Pragma("unroll")                                                      \
        for (int i_ = 0; i_ < 2; i_++) {                                       \
            int slot_ = tid + (i_ << 8);                                       \
            int r_ = slot_ >> 3, c8_ = (slot_ & 7) << 3;                       \
            uint32_t so_ = (uint32_t)((buf) * 64 * LDS + r_ * LDS + c8_) * 2;  \
            cpa16(ks0 + so_, kg + (size_t)(n0_ + r_) * 64 + c8_);              \
            cpa16(vs0 + so_, vg + (size_t)(n0_ + r_) * 64 + c8_);              \
        }                                                                      \
        CP_COMMIT();                                                           \
    } while (0)

    // number of 64-wide KV tiles: cover rows up to qbase+QT
    const int T = (qbase + QT) / 64;         // = 2*(qt+1)
    FKV_LOAD(0, 0);

    const int gid = lane >> 2, t4 = lane & 3;
    const int qg0 = qbase + w * 16 + gid;

    uint32_t aQ[4][4];
    float oacc[8][4];
    #pragma unroll
    for (int i = 0; i < 8; i++)
        #pragma unroll
        for (int j = 0; j < 4; j++) oacc[i][j] = 0.f;
    float m0 = NEG_BIG, m1 = NEG_BIG, l0 = 0.f, l1 = 0.f;

    const int arow = lane & 15;
    const int acolo = (lane >> 4) << 3;
    const int bro = lane & 7;
    const int bcolo = ((lane >> 3) & 1) << 3;
    const int l15 = lane & 15;

    for (int t = 0; t < T; t++) {
        const int buf = t & 1;
        if (t + 1 < T) { FKV_LOAD(t + 1, buf ^ 1); CP_WAIT1(); }
        else           { CP_WAIT0(); }
        __syncthreads();

        if (t == 0) {
            #pragma unroll
            for (int k = 0; k < 4; k++) {
                uint32_t ad = qs + (uint32_t)((w * 16 + arow) * LDS + k * 16 + acolo) * 2;
                ldm_x4(aQ[k], ad);
            }
        }

        const uint32_t kb = ks0 + (uint32_t)(buf * 64 * LDS) * 2;
        const uint32_t vb = vs0 + (uint32_t)(buf * 64 * LDS) * 2;
        const int n0 = t * 64;

        // skip tiles strictly above this warp's causal range
        if (n0 > qbase + w * 16 + 15) { __syncthreads(); continue; }

        float sacc[8][4];
        #pragma unroll
        for (int i = 0; i < 8; i++)
            #pragma unroll
            for (int j = 0; j < 4; j++) sacc[i][j] = 0.f;

        #pragma unroll
        for (int k = 0; k < 4; k++) {
            #pragma unroll
            for (int nt = 0; nt < 8; nt++) {
                uint32_t bk[2];
                uint32_t bd = kb + (uint32_t)((nt * 8 + bro) * LDS + k * 16 + bcolo) * 2;
                ldm_x2(bk, bd);
                MMAH(sacc[nt], aQ[k], bk);
            }
        }

        const bool diag = (n0 + 63 >= qg0);  // tile may touch causal boundary for this warp
        #pragma unroll
        for (int nt = 0; nt < 8; nt++) {
            int kvb = n0 + nt * 8 + t4 * 2;
            #pragma unroll
            for (int c = 0; c < 2; c++) {
                float s0 = sacc[nt][c]   * 0.125f;
                float s1 = sacc[nt][c+2] * 0.125f;
                if (diag) {
                    if (kvb + c > qg0)     s0 = NEG_BIG;
                    if (kvb + c > qg0 + 8) s1 = NEG_BIG;
                }
                sacc[nt][c]   = s0;
                sacc[nt][c+2] = s1;
            }
        }

        float vmax0 = NEG_BIG, vmax1 = NEG_BIG;
        #pragma unroll
        for (int nt = 0; nt < 8; nt++) {
            vmax0 = fmaxf(vmax0, fmaxf(sacc[nt][0], sacc[nt][1]));
            vmax1 = fmaxf(vmax1, fmaxf(sacc[nt][2], sacc[nt][3]));
        }
        vmax0 = fmaxf(vmax0, __shfl_xor_sync(0xffffffffu, vmax0, 1));
        vmax0 = fmaxf(vmax0, __shfl_xor_sync(0xffffffffu, vmax0, 2));
        vmax1 = fmaxf(vmax1, __shfl_xor_sync(0xffffffffu, vmax1, 1));
        vmax1 = fmaxf(vmax1, __shfl_xor_sync(0xffffffffu, vmax1, 2));

        float mn0 = fmaxf(m0, vmax0), mn1 = fmaxf(m1, vmax1);
        float corr0 = __expf(m0 - mn0), corr1 = __expf(m1 - mn1);
        m0 = mn0; m1 = mn1;

        float lsum0 = 0.f, lsum1 = 0.f;
        #pragma unroll
        for (int nt = 0; nt < 8; nt++) {
            float p0 = __expf(sacc[nt][0] - mn0);
            float p1 = __expf(sacc[nt][1] - mn0);
            float p2 = __expf(sacc[nt][2] - mn1);
            float p3 = __expf(sacc[nt][3] - mn1);
            sacc[nt][0] = p0; sacc[nt][1] = p1; sacc[nt][2] = p2; sacc[nt][3] = p3;
            lsum0 += p0 + p1; lsum1 += p2 + p3;
        }
        lsum0 += __shfl_xor_sync(0xffffffffu, lsum0, 1);
        lsum0 += __shfl_xor_sync(0xffffffffu, lsum0, 2);
        lsum1 += __shfl_xor_sync(0xffffffffu, lsum1, 1);
        lsum1 += __shfl_xor_sync(0xffffffffu, lsum1, 2);
        l0 = l0 * corr0 + lsum0;
        l1 = l1 * corr1 + lsum1;

        #pragma unroll
        for (int nt = 0; nt < 8; nt++) {
            oacc[nt][0] *= corr0; oacc[nt][1] *= corr0;
            oacc[nt][2] *= corr1; oacc[nt][3] *= corr1;
        }

        #pragma unroll
        for (int kp = 0; kp < 4; kp++) {
            uint32_t pa[4];
            pa[0] = packh(sacc[2*kp][0],   sacc[2*kp][1]);
            pa[1] = packh(sacc[2*kp][2],   sacc[2*kp][3]);
            pa[2] = packh(sacc[2*kp+1][0], sacc[2*kp+1][1]);
            pa[3] = packh(sacc[2*kp+1][2], sacc[2*kp+1][3]);
            #pragma unroll
            for (int ntd = 0; ntd < 8; ntd++) {
                uint32_t bv[2];
                uint32_t vd = vb + (uint32_t)((kp * 16 + l15) * LDS + ntd * 8) * 2;
                ldm_x2t(bv, vd);
                MMAH(oacc[ntd], pa, bv);
            }
        }
        __syncthreads();
    }

    float invl0 = 1.f / l0, invl1 = 1.f / l1;
    const size_t row0 = (size_t)(b * SEQ + qbase + w * 16 + gid);
    #pragma unroll
    for (int ntd = 0; ntd < 8; ntd++) {
        int col = h * 64 + ntd * 8 + t4 * 2;
        *(__half2*)(ah + row0 * DM + col) =
            __floats2half2_rn(oacc[ntd][0] * invl0, oacc[ntd][1] * invl0);
        *(__half2*)(ah + (row0 + 8) * DM + col) =
            __floats2half2_rn(oacc[ntd][2] * invl1, oacc[ntd][3] * invl1);
    }
}

// ================= launch =================
extern "C" void kernel_launch(void* const* d_in, const int* in_sizes, int n_in,
                              void* d_out, int out_size)
{
    const float* x      = (const float*)d_in[0];
    const float* qkv_w  = (const float*)d_in[2];
    const float* o_w    = (const float*)d_in[3];
    const float* gain1  = (const float*)d_in[4];
    const float* gain2  = (const float*)d_in[5];
    const float* w1     = (const float*)d_in[6];
    const float* w2     = (const float*)d_in[7];
    const float* w3     = (const float*)d_in[8];
    float* out = (float*)d_out;

    float *h1, *hb, *gb, *rt, *xn;
    __half *ah, *wh;
    cudaGetSymbolAddress((void**)&h1,  g_h1);
    cudaGetSymbolAddress((void**)&xn,  g_xn);
    cudaGetSymbolAddress((void**)&hb,  g_h);
    cudaGetSymbolAddress((void**)&gb,  g_g);
    cudaGetSymbolAddress((void**)&rt,  g_rt);
    cudaGetSymbolAddress((void**)&ah,  g_ah);
    cudaGetSymbolAddress((void**)&wh,  g_wh);

    __half* qhb = (__half*)xn;
    __half* khb = (__half*)xn + (size_t)MROWS*DM;
    __half* vhb = (__half*)hb;
    __half* sgh = (__half*)gb;      // silu-product fp16

    cudaFuncSetAttribute(gemmh_k,      cudaFuncAttributeMaxDynamicSharedMemorySize, SMEMB);
    cudaFuncSetAttribute(gemmqkv_k,    cudaFuncAttributeMaxDynamicSharedMemorySize, SMEMB);
    cudaFuncSetAttribute(gemmw3silu_k, cudaFuncAttributeMaxDynamicSharedMemorySize, SMEMB);
    cudaFuncSetAttribute(flashm_k,     cudaFuncAttributeMaxDynamicSharedMemorySize, FSMEM);

    ropetab_k<<<(SEQ*32 + 255)/256, 256>>>(rt);
    conv_pad_k<<<(3145728/4 + 255)/256, 256>>>(qkv_w, wh+OQKV, 3072,1024,3072,1024);
    rmsnorm_h_k<<<MROWS, 256>>>(x, gain1, ah);
    gemmqkv_k<<<dim3(3072/128, MROWS/128), 256, SMEMB>>>(ah, wh+OQKV, rt, qhb, khb, vhb);
    flashm_k<<<dim3(SEQ/QT, BATCH*NH), 256, FSMEM>>>(qhb, khb, vhb, ah);
    conv_pad_k<<<(1048576/4 + 255)/256, 256>>>(o_w, wh+OO, 1024,1024,1024,1024);
    gemmh_k<<<dim3(DM/128, MROWS/128), 256, SMEMB>>>(ah, wh+OO, h1, x, DM, DM);
    rmsnorm_h_k<<<MROWS, 256>>>(h1, gain2, ah);
    conv_pad_k<<<((DFP*1024)/4 + 255)/256, 256>>>(w1, wh+OW1, DFF,1024,DFP,1024);
    conv_pad_k<<<((DFP*1024)/4 + 255)/256, 256>>>(w3, wh+OW3, DFF,1024,DFP,1024);
    gemmh_k<<<dim3(DFP/128, MROWS/128), 256, SMEMB>>>(ah, wh+OW1, hb, nullptr, DFP, DM);
    gemmw3silu_k<<<dim3(DFP/128, MROWS/128), 256, SMEMB>>>(ah, wh+OW3, hb, sgh, DFP, DM);
    conv_pad_k<<<((1024*DFP)/4 + 255)/256, 256>>>(w2, wh+OW2, 1024,DFF,1024,DFP);
    gemmh_k<<<dim3(DM/128, MROWS/128), 256, SMEMB>>>(sgh, wh+OW2, out, h1, DM, DFP);
}

// round 14
// speedup vs baseline: 1.1367x; 1.0131x over previous
#include <cuda_runtime.h>
#include <cuda_fp16.h>
#include <math.h>
#include <stdint.h>

#define BATCH 4
#define SEQ   2048
#define DM    1024
#define DFF   2752
#define DFP   2816
#define NH    16
#define DK    64
#define MROWS (BATCH*SEQ)

// ================= scratch =================
__device__ float g_h1 [(size_t)MROWS*DM];
__device__ float g_xn [(size_t)MROWS*DM];    // qhb+khb (fp16) during attention
__device__ float g_h  [(size_t)MROWS*DFP];   // vhb (fp16), then hb fp32
__device__ float g_g  [(size_t)MROWS*DFP];   // silu-product fp16 arena
__device__ float g_rt [SEQ*32*2];
__device__ __half g_ah[(size_t)MROWS*DFP];   // fp16 activation (GEMM A operand)
#define NWELEM 12845056
__device__ __half g_wh[(size_t)NWELEM];
#define OQKV 0
#define OO   3145728
#define OW1  4194304
#define OW3  7077888
#define OW2  9961472

// ================= PTX helpers =================
__device__ __forceinline__ uint32_t smem_u32(const void* p) {
    uint32_t a;
    asm("{ .reg .u64 t; cvta.to.shared.u64 t, %1; cvt.u32.u64 %0, t; }" : "=r"(a) : "l"(p));
    return a;
}
__device__ __forceinline__ void cpa16(uint32_t s, const void* g) {
    asm volatile("cp.async.cg.shared.global [%0], [%1], 16;" :: "r"(s), "l"(g));
}
#define CP_COMMIT() asm volatile("cp.async.commit_group;" ::: "memory")
#define CP_WAIT1()  asm volatile("cp.async.wait_group 1;" ::: "memory")
#define CP_WAIT0()  asm volatile("cp.async.wait_group 0;" ::: "memory")

__device__ __forceinline__ void ldm_x4(uint32_t* r, uint32_t a) {
    asm volatile("ldmatrix.sync.aligned.m8n8.x4.shared.b16 {%0,%1,%2,%3}, [%4];"
                 : "=r"(r[0]), "=r"(r[1]), "=r"(r[2]), "=r"(r[3]) : "r"(a));
}
__device__ __forceinline__ void ldm_x2(uint32_t* r, uint32_t a) {
    asm volatile("ldmatrix.sync.aligned.m8n8.x2.shared.b16 {%0,%1}, [%2];"
                 : "=r"(r[0]), "=r"(r[1]) : "r"(a));
}
__device__ __forceinline__ void ldm_x2t(uint32_t* r, uint32_t a) {
    asm volatile("ldmatrix.sync.aligned.m8n8.x2.trans.shared.b16 {%0,%1}, [%2];"
                 : "=r"(r[0]), "=r"(r[1]) : "r"(a));
}
// fp16 inputs, fp32 accumulate
#define MMAH(d, a, b) \
    asm volatile("mma.sync.aligned.m16n8k16.row.col.f32.f16.f16.f32 " \
        "{%0,%1,%2,%3}, {%4,%5,%6,%7}, {%8,%9}, {%0,%1,%2,%3};" \
        : "+f"((d)[0]), "+f"((d)[1]), "+f"((d)[2]), "+f"((d)[3]) \
        : "r"((a)[0]), "r"((a)[1]), "r"((a)[2]), "r"((a)[3]), "r"((b)[0]), "r"((b)[1]))

__device__ __forceinline__ uint32_t packh(float a, float b) {
    __half2 t = __floats2half2_rn(a, b);
    return *(uint32_t*)&t;
}

// ================= rope table =================
__global__ __launch_bounds__(256) void ropetab_k(float* __restrict__ rt)
{
    int idx = blockIdx.x * 256 + threadIdx.x;
    if (idx >= SEQ * 32) return;
    int s = idx >> 5, p = idx & 31;
    double inv = exp(-(double)(2 * p) * (9.210340371976184 / 64.0));
    double sd, cd;
    sincos((double)s * inv, &sd, &cd);
    rt[idx * 2]     = (float)cd;
    rt[idx * 2 + 1] = (float)sd;
}

// ================= weight convert fp32 -> fp16 (zero-padded) =================
__global__ __launch_bounds__(256) void conv_pad_k(const float* __restrict__ src,
                                                  __half* __restrict__ dst,
                                                  int srows, int scols,
                                                  int drows, int dcols)
{
    int i = blockIdx.x * 256 + threadIdx.x;
    int n4 = drows * (dcols >> 2);
    if (i >= n4) return;
    int r  = i / (dcols >> 2);
    int c4 = (i - r * (dcols >> 2)) << 2;
    float4 v = make_float4(0.f, 0.f, 0.f, 0.f);
    if (r < srows && c4 < scols)
        v = *(const float4*)(src + (size_t)r * scols + c4);
    size_t o = (size_t)r * dcols + c4;
    ((__half2*)(dst + o))[0] = __floats2half2_rn(v.x, v.y);
    ((__half2*)(dst + o))[1] = __floats2half2_rn(v.z, v.w);
}

// ================= RMSNorm -> fp16 =================
__global__ __launch_bounds__(256) void rmsnorm_h_k(const float* __restrict__ x,
                                                   const float* __restrict__ gain,
                                                   __half* __restrict__ outh)
{
    int row = blockIdx.x;
    const float4* xr = (const float4*)(x + (size_t)row * DM);
    float4 v = xr[threadIdx.x];
    float ss = v.x*v.x + v.y*v.y + v.z*v.z + v.w*v.w;
    #pragma unroll
    for (int o = 16; o; o >>= 1) ss += __shfl_xor_sync(0xffffffffu, ss, o);
    __shared__ float red[8];
    __shared__ float rinv;
    if ((threadIdx.x & 31) == 0) red[threadIdx.x >> 5] = ss;
    __syncthreads();
    if (threadIdx.x == 0) {
        float t = 0.f;
        #pragma unroll
        for (int i = 0; i < 8; i++) t += red[i];
        rinv = rsqrtf(t * (1.0f / DM) + 1e-5f);
    }
    __syncthreads();
    float r = rinv;
    float4 g = ((const float4*)gain)[threadIdx.x];
    size_t base = (size_t)row * (DM/2) + threadIdx.x * 2;
    ((__half2*)outh)[base]   = __floats2half2_rn(v.x*g.x*r, v.y*g.y*r);
    ((__half2*)outh)[base+1] = __floats2half2_rn(v.z*g.z*r, v.w*g.w*r);
}

// ======== fp16 HMMA GEMM core (128x128x32, 256 thr, 2 CTAs/SM) ========
#define GBK 32
#define LDT 40
#define TBUF (128*LDT)            /* halves per tile (10240 B) */
#define SMEMB (4 * TBUF * 2)      /* 40960 B: 2 bufs x (A + B) */

#define GLOAD_STAGE(s, buf)                                                    \
    do {                                                                       \
        int k0_ = (s) * GBK;                                                   \
        _Pragma("unroll")                                                      \
        for (int i_ = 0; i_ < 2; i_++) {                                       \
            int r_ = row + i_ * 64;                                            \
            size_t ga_ = (size_t)(bm + r_) * K + k0_ + kc;                     \
            size_t gb_ = (size_t)(bn + r_) * K + k0_ + kc;                     \
            uint32_t sa_ = smb + (uint32_t)(((buf))*TBUF + r_*LDT + kc)*2;     \
            uint32_t sb_ = smb + (uint32_t)((2+(buf))*TBUF + r_*LDT + kc)*2;   \
            cpa16(sa_, Ah + ga_);                                              \
            cpa16(sb_, Bh + gb_);                                              \
        }                                                                      \
        CP_COMMIT();                                                           \
    } while (0)

#define GEMM_MAIN()                                                            \
    float acc[4][4][4];                                                        \
    _Pragma("unroll")                                                          \
    for (int a_ = 0; a_ < 4; a_++)                                             \
        _Pragma("unroll")                                                      \
        for (int b_ = 0; b_ < 4; b_++)                                         \
            _Pragma("unroll")                                                  \
            for (int c_ = 0; c_ < 4; c_++) acc[a_][b_][c_] = 0.f;              \
    const int row = tid >> 2;                                                  \
    const int kc  = (tid & 3) << 3;                                            \
    const int NS = K / GBK;                                                    \
    GLOAD_STAGE(0, 0);                                                         \
    GLOAD_STAGE(1, 1);                                                         \
    const int arow = lane & 15;                                                \
    const int acolo = ((lane >> 4) << 3);                                      \
    const int bro  = lane & 7;                                                 \
    const int bcolo = (((lane >> 3) & 1) << 3);                                \
    for (int s = 0; s < NS; s++) {                                             \
        const int buf = s & 1;                                                 \
        CP_WAIT1();                                                            \
        __syncthreads();                                                       \
        const uint32_t aoff = smb + (uint32_t)(buf*TBUF)*2;                    \
        const uint32_t boff = smb + (uint32_t)((2 + buf)*TBUF)*2;              \
        _Pragma("unroll")                                                      \
        for (int ks = 0; ks < 2; ks++) {                                       \
            const int k0 = ks * 16;                                            \
            uint32_t aH[4][4], bH[4][2];                                       \
            _Pragma("unroll")                                                  \
            for (int mt = 0; mt < 4; mt++) {                                   \
                int r = wm * 64 + mt * 16 + arow;                              \
                ldm_x4(aH[mt], aoff + (uint32_t)(r * LDT + k0 + acolo) * 2);   \
            }                                                                  \
            _Pragma("unroll")                                                  \
            for (int nt = 0; nt < 4; nt++) {                                   \
                int n = wn * 32 + nt * 8 + bro;                                \
                ldm_x2(bH[nt], boff + (uint32_t)(n * LDT + k0 + bcolo) * 2);   \
            }                                                                  \
            _Pragma("unroll")                                                  \
            for (int mt = 0; mt < 4; mt++)                                     \
                _Pragma("unroll")                                              \
                for (int nt = 0; nt < 4; nt++)                                 \
                    MMAH(acc[mt][nt], aH[mt], bH[nt]);                         \
        }                                                                      \
        __syncthreads();                                                       \
        if (s + 2 < NS) GLOAD_STAGE(s + 2, buf);                               \
    }

#define GEMM_PREAMBLE()                                                        \
    extern __shared__ __align__(128) __half sm[];                              \
    const uint32_t smb = smem_u32(sm);                                         \
    const int tid  = threadIdx.x;                                              \
    const int lane = tid & 31;                                                 \
    const int wid  = tid >> 5;                                                 \
    const int wm   = wid >> 2;                                                 \
    const int wn   = wid & 3;                                                  \
    const int bm   = blockIdx.y * 128;                                         \
    const int bn   = blockIdx.x * 128;

__global__ __launch_bounds__(256, 2) void gemmh_k(
    const __half* __restrict__ Ah, const __half* __restrict__ Bh,
    float* __restrict__ C, const float* __restrict__ res, int N, int K)
{
    GEMM_PREAMBLE();
    GEMM_MAIN();

    const int gid = lane >> 2, t4 = lane & 3;
    #pragma unroll
    for (int mt = 0; mt < 4; mt++) {
        int r0 = bm + wm * 64 + mt * 16 + gid;
        #pragma unroll
        for (int nt = 0; nt < 4; nt++) {
            int col = bn + wn * 32 + nt * 8 + t4 * 2;
            size_t o0 = (size_t)r0 * N + col;
            size_t o1 = o0 + (size_t)8 * N;
            float2 v0 = make_float2(acc[mt][nt][0], acc[mt][nt][1]);
            float2 v1 = make_float2(acc[mt][nt][2], acc[mt][nt][3]);
            if (res) {
                float2 r0v = *(const float2*)(res + o0);
                float2 r1v = *(const float2*)(res + o1);
                v0.x += r0v.x; v0.y += r0v.y;
                v1.x += r1v.x; v1.y += r1v.y;
            }
            *(float2*)(C + o0) = v0;
            *(float2*)(C + o1) = v1;
        }
    }
}

// ======== w3 GEMM with fused SiLU: out = silu(hb) * acc, fp16 ========
__global__ __launch_bounds__(256, 2) void gemmw3silu_k(
    const __half* __restrict__ Ah, const __half* __restrict__ Bh,
    const float* __restrict__ hb, __half* __restrict__ outh, int N, int K)
{
    GEMM_PREAMBLE();
    GEMM_MAIN();

    const int gid = lane >> 2, t4 = lane & 3;
    #pragma unroll
    for (int mt = 0; mt < 4; mt++) {
        int r0 = bm + wm * 64 + mt * 16 + gid;
        #pragma unroll
        for (int nt = 0; nt < 4; nt++) {
            int col = bn + wn * 32 + nt * 8 + t4 * 2;
            size_t o0 = (size_t)r0 * N + col;
            size_t o1 = o0 + (size_t)8 * N;
            float2 h0 = *(const float2*)(hb + o0);
            float2 h1 = *(const float2*)(hb + o1);
            float y0 = acc[mt][nt][0] * h0.x / (1.f + __expf(-h0.x));
            float y1 = acc[mt][nt][1] * h0.y / (1.f + __expf(-h0.y));
            float y2 = acc[mt][nt][2] * h1.x / (1.f + __expf(-h1.x));
            float y3 = acc[mt][nt][3] * h1.y / (1.f + __expf(-h1.y));
            *(__half2*)(outh + o0) = __floats2half2_rn(y0, y1);
            *(__half2*)(outh + o1) = __floats2half2_rn(y2, y3);
        }
    }
}

// ======== QKV GEMM with fused RoPE + head-major fp16 output ========
__global__ __launch_bounds__(256, 2) void gemmqkv_k(
    const __half* __restrict__ Ah, const __half* __restrict__ Bh,
    const float* __restrict__ rt,
    __half* __restrict__ qhb, __half* __restrict__ khb,
    __half* __restrict__ vhb)
{
    const int K = DM;
    GEMM_PREAMBLE();
    GEMM_MAIN();

    const int gid = lane >> 2, t4 = lane & 3;
    #pragma unroll
    for (int mt = 0; mt < 4; mt++) {
        int r0 = bm + wm * 64 + mt * 16 + gid;
        #pragma unroll
        for (int nt = 0; nt < 4; nt++) {
            int col = bn + wn * 32 + nt * 8 + t4 * 2;
            int t   = col >> 10;
            int rem = col & 1023;
            int hh  = rem >> 6;
            int d   = rem & 63;
            int p   = d >> 1;
            __half* dstbuf = (t == 0) ? qhb : (t == 1) ? khb : vhb;
            #pragma unroll
            for (int half_ = 0; half_ < 2; half_++) {
                int r = r0 + half_ * 8;
                float v0 = acc[mt][nt][half_ * 2];
                float v1 = acc[mt][nt][half_ * 2 + 1];
                int s = r & (SEQ - 1);
                int b = r >> 11;
                size_t dst = ((size_t)(b * NH + hh) * SEQ + s) * DK + d;
                if (t < 2) {
                    float2 cs = ((const float2*)rt)[s * 32 + p];
                    float x0 = cs.x * v0 - cs.y * v1;
                    float x1 = cs.y * v0 + cs.x * v1;
                    v0 = x0; v1 = x1;
                }
                *(__half2*)(dstbuf + dst) = __floats2half2_rn(v0, v1);
            }
        }
    }
}

// ================= fp16 HMMA flash attention (QT=64, 128 thr — round-11 exact) =================
#define QT 64
#define LDS 72
#define NEG_BIG (-1.0e30f)

__global__ __launch_bounds__(128) void flashm_k(const __half* __restrict__ qhb,
                                                const __half* __restrict__ khb,
                                                const __half* __restrict__ vhb,
                                                __half* __restrict__ ah)
{
    __shared__ __align__(128) __half Qs[QT * LDS];
    __shared__ __align__(128) __half Ks[2][64 * LDS];
    __shared__ __align__(128) __half Vs[2][64 * LDS];

    const int tid  = threadIdx.x;
    const int lane = tid & 31;
    const int w    = tid >> 5;
    const int bh   = blockIdx.y;
    const int b    = bh >> 4, h = bh & 15;
    const int qt   = gridDim.x - 1 - blockIdx.x;
    const int qbase = qt * QT;

    const uint32_t qs = smem_u32(Qs);
    const uint32_t ks0 = smem_u32(Ks);
    const uint32_t vs0 = smem_u32(Vs);

    const __half* qg = qhb + ((size_t)bh * SEQ + qbase) * DK;
    #pragma unroll
    for (int i = 0; i < 4; i++) {
        int slot = tid + (i << 7);
        int r = slot >> 3, c8 = (slot & 7) << 3;
        cpa16(qs + (uint32_t)(r * LDS + c8) * 2, qg + r * 64 + c8);
    }
    CP_COMMIT();

    const __half* kg = khb + (size_t)bh * SEQ * DK;
    const __half* vg = vhb + (size_t)bh * SEQ * DK;

    #define FKV_LOAD(t, buf) do {                                              \
        int n0_ = (t) * 64;                                                    \
        _Pragma("unroll")                                                      \
        for (int i_ = 0; i_ < 4; i_++) {                                       \
            int slot_ = tid + (i_ << 7);                                       \
            int r_ = slot_ >> 3, c8_ = (slot_ & 7) << 3;                       \
            uint32_t so_ = (uint32_t)((buf) * 64 * LDS + r_ * LDS + c8_) * 2;  \
            cpa16(ks0 + so_, kg + (size_t)(n0_ + r_) * 64 + c8_);              \
            cpa16(vs0 + so_, vg + (size_t)(n0_ + r_) * 64 + c8_);              \
        }                                                                      \
        CP_COMMIT();                                                           \
    } while (0)

    const int T = qt + 1;
    FKV_LOAD(0, 0);

    const int gid = lane >> 2, t4 = lane & 3;
    const int qg0 = qbase + w * 16 + gid;

    uint32_t aQ[4][4];
    float oacc[8][4];
    #pragma unroll
    for (int i = 0; i < 8; i++)
        #pragma unroll
        for (int j = 0; j < 4; j++) oacc[i][j] = 0.f;
    float m0 = NEG_BIG, m1 = NEG_BIG, l0 = 0.f, l1 = 0.f;

    const int arow = lane & 15;
    const int acolo = (lane >> 4) << 3;
    const int bro = lane & 7;
    const int bcolo = ((lane >> 3) & 1) << 3;
    const int l15 = lane & 15;

    for (int t = 0; t < T; t++) {
        const int buf = t & 1;
        if (t + 1 < T) { FKV_LOAD(t + 1, buf ^ 1); CP_WAIT1(); }
        else           { CP_WAIT0(); }
        __syncthreads();

        if (t == 0) {
            #pragma unroll
            for (int k = 0; k < 4; k++) {
                uint32_t ad = qs + (uint32_t)((w * 16 + arow) * LDS + k * 16 + acolo) * 2;
                ldm_x4(aQ[k], ad);
            }
        }

        const uint32_t kb = ks0 + (uint32_t)(buf * 64 * LDS) * 2;
        const uint32_t vb = vs0 + (uint32_t)(buf * 64 * LDS) * 2;
        const int n0 = t * 64;

        float sacc[8][4];
        #pragma unroll
        for (int i = 0; i < 8; i++)
            #pragma unroll
            for (int j = 0; j < 4; j++) sacc[i][j] = 0.f;

        #pragma unroll
        for (int k = 0; k < 4; k++) {
            #pragma unroll
            for (int nt = 0; nt < 8; nt++) {
                uint32_t bk[2];
                uint32_t bd = kb + (uint32_t)((nt * 8 + bro) * LDS + k * 16 + bcolo) * 2;
                ldm_x2(bk, bd);
                MMAH(sacc[nt], aQ[k], bk);
            }
        }

        const bool diag = (t == qt);
        #pragma unroll
        for (int nt = 0; nt < 8; nt++) {
            int kvb = n0 + nt * 8 + t4 * 2;
            #pragma unroll
            for (int c = 0; c < 2; c++) {
                float s0 = sacc[nt][c]   * 0.125f;
                float s1 = sacc[nt][c+2] * 0.125f;
                if (diag) {
                    if (kvb + c > qg0)     s0 = NEG_BIG;
                    if (kvb + c > qg0 + 8) s1 = NEG_BIG;
                }
                sacc[nt][c]   = s0;
                sacc[nt][c+2] = s1;
            }
        }

        float vmax0 = NEG_BIG, vmax1 = NEG_BIG;
        #pragma unroll
        for (int nt = 0; nt < 8; nt++) {
            vmax0 = fmaxf(vmax0, fmaxf(sacc[nt][0], sacc[nt][1]));
            vmax1 = fmaxf(vmax1, fmaxf(sacc[nt][2], sacc[nt][3]));
        }
        vmax0 = fmaxf(vmax0, __shfl_xor_sync(0xffffffffu, vmax0, 1));
        vmax0 = fmaxf(vmax0, __shfl_xor_sync(0xffffffffu, vmax0, 2));
        vmax1 = fmaxf(vmax1, __shfl_xor_sync(0xffffffffu, vmax1, 1));
        vmax1 = fmaxf(vmax1, __shfl_xor_sync(0xffffffffu, vmax1, 2));

        float mn0 = fmaxf(m0, vmax0), mn1 = fmaxf(m1, vmax1);
        float corr0 = __expf(m0 - mn0), corr1 = __expf(m1 - mn1);
        m0 = mn0; m1 = mn1;

        float lsum0 = 0.f, lsum1 = 0.f;
        #pragma unroll
        for (int nt = 0; nt < 8; nt++) {
            float p0 = __expf(sacc[nt][0] - mn0);
            float p1 = __expf(sacc[nt][1] - mn0);
            float p2 = __expf(sacc[nt][2] - mn1);
            float p3 = __expf(sacc[nt][3] - mn1);
            sacc[nt][0] = p0; sacc[nt][1] = p1; sacc[nt][2] = p2; sacc[nt][3] = p3;
            lsum0 += p0 + p1; lsum1 += p2 + p3;
        }
        lsum0 += __shfl_xor_sync(0xffffffffu, lsum0, 1);
        lsum0 += __shfl_xor_sync(0xffffffffu, lsum0, 2);
        lsum1 += __shfl_xor_sync(0xffffffffu, lsum1, 1);
        lsum1 += __shfl_xor_sync(0xffffffffu, lsum1, 2);
        l0 = l0 * corr0 + lsum0;
        l1 = l1 * corr1 + lsum1;

        #pragma unroll
        for (int nt = 0; nt < 8; nt++) {
            oacc[nt][0] *= corr0; oacc[nt][1] *= corr0;
            oacc[nt][2] *= corr1; oacc[nt][3] *= corr1;
        }

        #pragma unroll
        for (int kp = 0; kp < 4; kp++) {
            uint32_t pa[4];
            pa[0] = packh(sacc[2*kp][0],   sacc[2*kp][1]);
            pa[1] = packh(sacc[2*kp][2],   sacc[2*kp][3]);
            pa[2] = packh(sacc[2*kp+1][0], sacc[2*kp+1][1]);
            pa[3] = packh(sacc[2*kp+1][2], sacc[2*kp+1][3]);
            #pragma unroll
            for (int ntd = 0; ntd < 8; ntd++) {
                uint32_t bv[2];
                uint32_t vd = vb + (uint32_t)((kp * 16 + l15) * LDS + ntd * 8) * 2;
                ldm_x2t(bv, vd);
                MMAH(oacc[ntd], pa, bv);
            }
        }
        __syncthreads();
    }

    float invl0 = 1.f / l0, invl1 = 1.f / l1;
    const size_t row0 = (size_t)(b * SEQ + qbase + w * 16 + gid);
    #pragma unroll
    for (int ntd = 0; ntd < 8; ntd++) {
        int col = h * 64 + ntd * 8 + t4 * 2;
        *(__half2*)(ah + row0 * DM + col) =
            __floats2half2_rn(oacc[ntd][0] * invl0, oacc[ntd][1] * invl0);
        *(__half2*)(ah + (row0 + 8) * DM + col) =
            __floats2half2_rn(oacc[ntd][2] * invl1, oacc[ntd][3] * invl1);
    }
}

// ================= launch =================
extern "C" void kernel_launch(void* const* d_in, const int* in_sizes, int n_in,
                              void* d_out, int out_size)
{
    const float* x      = (const float*)d_in[0];
    const float* qkv_w  = (const float*)d_in[2];
    const float* o_w    = (const float*)d_in[3];
    const float* gain1  = (const float*)d_in[4];
    const float* gain2  = (const float*)d_in[5];
    const float* w1     = (const float*)d_in[6];
    const float* w2     = (const float*)d_in[7];
    const float* w3     = (const float*)d_in[8];
    float* out = (float*)d_out;

    float *h1, *hb, *gb, *rt, *xn;
    __half *ah, *wh;
    cudaGetSymbolAddress((void**)&h1,  g_h1);
    cudaGetSymbolAddress((void**)&xn,  g_xn);
    cudaGetSymbolAddress((void**)&hb,  g_h);
    cudaGetSymbolAddress((void**)&gb,  g_g);
    cudaGetSymbolAddress((void**)&rt,  g_rt);
    cudaGetSymbolAddress((void**)&ah,  g_ah);
    cudaGetSymbolAddress((void**)&wh,  g_wh);

    __half* qhb = (__half*)xn;
    __half* khb = (__half*)xn + (size_t)MROWS*DM;
    __half* vhb = (__half*)hb;
    __half* sgh = (__half*)gb;      // silu-product fp16

    cudaFuncSetAttribute(gemmh_k,      cudaFuncAttributeMaxDynamicSharedMemorySize, SMEMB);
    cudaFuncSetAttribute(gemmqkv_k,    cudaFuncAttributeMaxDynamicSharedMemorySize, SMEMB);
    cudaFuncSetAttribute(gemmw3silu_k, cudaFuncAttributeMaxDynamicSharedMemorySize, SMEMB);

    ropetab_k<<<(SEQ*32 + 255)/256, 256>>>(rt);
    conv_pad_k<<<(3145728/4 + 255)/256, 256>>>(qkv_w, wh+OQKV, 3072,1024,3072,1024);
    rmsnorm_h_k<<<MROWS, 256>>>(x, gain1, ah);
    gemmqkv_k<<<dim3(3072/128, MROWS/128), 256, SMEMB>>>(ah, wh+OQKV, rt, qhb, khb, vhb);
    flashm_k<<<dim3(SEQ/QT, BATCH*NH), 128>>>(qhb, khb, vhb, ah);
    conv_pad_k<<<(1048576/4 + 255)/256, 256>>>(o_w, wh+OO, 1024,1024,1024,1024);
    gemmh_k<<<dim3(DM/128, MROWS/128), 256, SMEMB>>>(ah, wh+OO, h1, x, DM, DM);
    rmsnorm_h_k<<<MROWS, 256>>>(h1, gain2, ah);
    conv_pad_k<<<((DFP*1024)/4 + 255)/256, 256>>>(w1, wh+OW1, DFF,1024,DFP,1024);
    conv_pad_k<<<((DFP*1024)/4 + 255)/256, 256>>>(w3, wh+OW3, DFF,1024,DFP,1024);
    gemmh_k<<<dim3(DFP/128, MROWS/128), 256, SMEMB>>>(ah, wh+OW1, hb, nullptr, DFP, DM);
    gemmw3silu_k<<<dim3(DFP/128, MROWS/128), 256, SMEMB>>>(ah, wh+OW3, hb, sgh, DFP, DM);
    conv_pad_k<<<((1024*DFP)/4 + 255)/256, 256>>>(w2, wh+OW2, 1024,DFF,1024,DFP);
    gemmh_k<<<dim3(DM/128, MROWS/128), 256, SMEMB>>>(sgh, wh+OW2, out, h1, DM, DFP);
}

// round 16
// speedup vs baseline: 1.2359x; 1.0873x over previous
#include <cuda_runtime.h>
#include <cuda_fp16.h>
#include <math.h>
#include <stdint.h>

#define BATCH 4
#define SEQ   2048
#define DM    1024
#define DFF   2752
#define DFP   2816
#define NH    16
#define DK    64
#define MROWS (BATCH*SEQ)

// ================= scratch =================
__device__ float g_h1 [(size_t)MROWS*DM];
__device__ float g_xn [(size_t)MROWS*DM];    // qhb+khb (fp16) during attention
__device__ float g_h  [(size_t)MROWS*DFP];   // vhb (fp16), then hb fp32
__device__ float g_g  [(size_t)MROWS*DFP];   // silu-product fp16 arena
__device__ float g_rt [SEQ*32*2];
__device__ __half g_ah[(size_t)MROWS*DFP];   // fp16 activation (GEMM A operand)
#define NWELEM 12845056
__device__ __half g_wh[(size_t)NWELEM];
#define OQKV 0
#define OO   3145728
#define OW1  4194304
#define OW3  7077888
#define OW2  9961472

// ================= PTX helpers =================
__device__ __forceinline__ uint32_t smem_u32(const void* p) {
    uint32_t a;
    asm("{ .reg .u64 t; cvta.to.shared.u64 t, %1; cvt.u32.u64 %0, t; }" : "=r"(a) : "l"(p));
    return a;
}
__device__ __forceinline__ void cpa16(uint32_t s, const void* g) {
    asm volatile("cp.async.cg.shared.global [%0], [%1], 16;" :: "r"(s), "l"(g));
}
#define CP_COMMIT() asm volatile("cp.async.commit_group;" ::: "memory")
#define CP_WAIT1()  asm volatile("cp.async.wait_group 1;" ::: "memory")
#define CP_WAIT0()  asm volatile("cp.async.wait_group 0;" ::: "memory")

__device__ __forceinline__ void ldm_x4(uint32_t* r, uint32_t a) {
    asm volatile("ldmatrix.sync.aligned.m8n8.x4.shared.b16 {%0,%1,%2,%3}, [%4];"
                 : "=r"(r[0]), "=r"(r[1]), "=r"(r[2]), "=r"(r[3]) : "r"(a));
}
__device__ __forceinline__ void ldm_x2(uint32_t* r, uint32_t a) {
    asm volatile("ldmatrix.sync.aligned.m8n8.x2.shared.b16 {%0,%1}, [%2];"
                 : "=r"(r[0]), "=r"(r[1]) : "r"(a));
}
__device__ __forceinline__ void ldm_x2t(uint32_t* r, uint32_t a) {
    asm volatile("ldmatrix.sync.aligned.m8n8.x2.trans.shared.b16 {%0,%1}, [%2];"
                 : "=r"(r[0]), "=r"(r[1]) : "r"(a));
}
// fp16 inputs, fp32 accumulate
#define MMAH(d, a, b) \
    asm volatile("mma.sync.aligned.m16n8k16.row.col.f32.f16.f16.f32 " \
        "{%0,%1,%2,%3}, {%4,%5,%6,%7}, {%8,%9}, {%0,%1,%2,%3};" \
        : "+f"((d)[0]), "+f"((d)[1]), "+f"((d)[2]), "+f"((d)[3]) \
        : "r"((a)[0]), "r"((a)[1]), "r"((a)[2]), "r"((a)[3]), "r"((b)[0]), "r"((b)[1]))

__device__ __forceinline__ uint32_t packh(float a, float b) {
    __half2 t = __floats2half2_rn(a, b);
    return *(uint32_t*)&t;
}

// ================= rope table =================
__global__ __launch_bounds__(256) void ropetab_k(float* __restrict__ rt)
{
    int idx = blockIdx.x * 256 + threadIdx.x;
    if (idx >= SEQ * 32) return;
    int s = idx >> 5, p = idx & 31;
    double inv = exp(-(double)(2 * p) * (9.210340371976184 / 64.0));
    double sd, cd;
    sincos((double)s * inv, &sd, &cd);
    rt[idx * 2]     = (float)cd;
    rt[idx * 2 + 1] = (float)sd;
}

// ================= weight convert fp32 -> fp16 (zero-padded) =================
__global__ __launch_bounds__(256) void conv_pad_k(const float* __restrict__ src,
                                                  __half* __restrict__ dst,
                                                  int srows, int scols,
                                                  int drows, int dcols)
{
    int i = blockIdx.x * 256 + threadIdx.x;
    int n4 = drows * (dcols >> 2);
    if (i >= n4) return;
    int r  = i / (dcols >> 2);
    int c4 = (i - r * (dcols >> 2)) << 2;
    float4 v = make_float4(0.f, 0.f, 0.f, 0.f);
    if (r < srows && c4 < scols)
        v = *(const float4*)(src + (size_t)r * scols + c4);
    size_t o = (size_t)r * dcols + c4;
    ((__half2*)(dst + o))[0] = __floats2half2_rn(v.x, v.y);
    ((__half2*)(dst + o))[1] = __floats2half2_rn(v.z, v.w);
}

// ================= RMSNorm -> fp16 =================
__global__ __launch_bounds__(256) void rmsnorm_h_k(const float* __restrict__ x,
                                                   const float* __restrict__ gain,
                                                   __half* __restrict__ outh)
{
    int row = blockIdx.x;
    const float4* xr = (const float4*)(x + (size_t)row * DM);
    float4 v = xr[threadIdx.x];
    float ss = v.x*v.x + v.y*v.y + v.z*v.z + v.w*v.w;
    #pragma unroll
    for (int o = 16; o; o >>= 1) ss += __shfl_xor_sync(0xffffffffu, ss, o);
    __shared__ float red[8];
    __shared__ float rinv;
    if ((threadIdx.x & 31) == 0) red[threadIdx.x >> 5] = ss;
    __syncthreads();
    if (threadIdx.x == 0) {
        float t = 0.f;
        #pragma unroll
        for (int i = 0; i < 8; i++) t += red[i];
        rinv = rsqrtf(t * (1.0f / DM) + 1e-5f);
    }
    __syncthreads();
    float r = rinv;
    float4 g = ((const float4*)gain)[threadIdx.x];
    size_t base = (size_t)row * (DM/2) + threadIdx.x * 2;
    ((__half2*)outh)[base]   = __floats2half2_rn(v.x*g.x*r, v.y*g.y*r);
    ((__half2*)outh)[base+1] = __floats2half2_rn(v.z*g.z*r, v.w*g.w*r);
}

// ======== fp16 HMMA GEMM core (128x128x32, 256 thr, 3-stage ring, 2 CTAs/SM) ========
#define GBK 32
#define LDT 40
#define TBUF (128*LDT)            /* halves per tile (10240 B) */
#define SMEMB (6 * TBUF * 2)      /* 61440 B: 3 bufs x (A + B) */

#define GLOAD_STAGE(s, buf)                                                    \
    do {                                                                       \
        int k0_ = (s) * GBK;                                                   \
        _Pragma("unroll")                                                      \
        for (int i_ = 0; i_ < 2; i_++) {                                       \
            int r_ = row + i_ * 64;                                            \
            size_t ga_ = (size_t)(bm + r_) * K + k0_ + kc;                     \
            size_t gb_ = (size_t)(bn + r_) * K + k0_ + kc;                     \
            uint32_t sa_ = smb + (uint32_t)(((buf))*TBUF + r_*LDT + kc)*2;     \
            uint32_t sb_ = smb + (uint32_t)((3+(buf))*TBUF + r_*LDT + kc)*2;   \
            cpa16(sa_, Ah + ga_);                                              \
            cpa16(sb_, Bh + gb_);                                              \
        }                                                                      \
        CP_COMMIT();                                                           \
    } while (0)

#define GEMM_MAIN()                                                            \
    float acc[4][4][4];                                                        \
    _Pragma("unroll")                                                          \
    for (int a_ = 0; a_ < 4; a_++)                                             \
        _Pragma("unroll")                                                      \
        for (int b_ = 0; b_ < 4; b_++)                                         \
            _Pragma("unroll")                                                  \
            for (int c_ = 0; c_ < 4; c_++) acc[a_][b_][c_] = 0.f;              \
    const int row = tid >> 2;                                                  \
    const int kc  = (tid & 3) << 3;                                            \
    const int NS = K / GBK;                                                    \
    GLOAD_STAGE(0, 0);                                                         \
    GLOAD_STAGE(1, 1);                                                         \
    const int arow = lane & 15;                                                \
    const int acolo = ((lane >> 4) << 3);                                      \
    const int bnoff = ((lane >> 1) & 8) + (lane & 7);  /* x4 B: n offset */    \
    const int bkoff = (lane & 8);                       /* x4 B: k offset */   \
    int nb = 2;                                                                \
    for (int s = 0; s < NS; s++) {                                             \
        const int buf = (s < 3) ? s : (s % 3);                                 \
        CP_WAIT1();                                                            \
        __syncthreads();                                                       \
        if (s + 2 < NS) { GLOAD_STAGE(s + 2, nb); nb = (nb == 2) ? 0 : nb + 1; } \
        const uint32_t aoff = smb + (uint32_t)(buf*TBUF)*2;                    \
        const uint32_t boff = smb + (uint32_t)((3 + buf)*TBUF)*2;              \
        _Pragma("unroll")                                                      \
        for (int ks = 0; ks < 2; ks++) {                                       \
            const int k0 = ks * 16;                                            \
            uint32_t aH[4][4], bH[4][2];                                       \
            _Pragma("unroll")                                                  \
            for (int mt = 0; mt < 4; mt++) {                                   \
                int r = wm * 64 + mt * 16 + arow;                              \
                ldm_x4(aH[mt], aoff + (uint32_t)(r * LDT + k0 + acolo) * 2);   \
            }                                                                  \
            _Pragma("unroll")                                                  \
            for (int n2 = 0; n2 < 2; n2++) {                                   \
                uint32_t bt[4];                                                \
                int n = wn * 32 + n2 * 16 + bnoff;                             \
                ldm_x4(bt, boff + (uint32_t)(n * LDT + k0 + bkoff) * 2);       \
                bH[n2*2][0]   = bt[0]; bH[n2*2][1]   = bt[1];                  \
                bH[n2*2+1][0] = bt[2]; bH[n2*2+1][1] = bt[3];                  \
            }                                                                  \
            _Pragma("unroll")                                                  \
            for (int mt = 0; mt < 4; mt++)                                     \
                _Pragma("unroll")                                              \
                for (int nt = 0; nt < 4; nt++)                                 \
                    MMAH(acc[mt][nt], aH[mt], bH[nt]);                         \
        }                                                                      \
    }

#define GEMM_PREAMBLE()                                                        \
    extern __shared__ __align__(128) __half sm[];                              \
    const uint32_t smb = smem_u32(sm);                                         \
    const int tid  = threadIdx.x;                                              \
    const int lane = tid & 31;                                                 \
    const int wid  = tid >> 5;                                                 \
    const int wm   = wid >> 2;                                                 \
    const int wn   = wid & 3;                                                  \
    const int bm   = blockIdx.y * 128;                                         \
    const int bn   = blockIdx.x * 128;

__global__ __launch_bounds__(256, 2) void gemmh_k(
    const __half* __restrict__ Ah, const __half* __restrict__ Bh,
    float* __restrict__ C, const float* __restrict__ res, int N, int K)
{
    GEMM_PREAMBLE();
    GEMM_MAIN();

    const int gid = lane >> 2, t4 = lane & 3;
    #pragma unroll
    for (int mt = 0; mt < 4; mt++) {
        int r0 = bm + wm * 64 + mt * 16 + gid;
        #pragma unroll
        for (int nt = 0; nt < 4; nt++) {
            int col = bn + wn * 32 + nt * 8 + t4 * 2;
            size_t o0 = (size_t)r0 * N + col;
            size_t o1 = o0 + (size_t)8 * N;
            float2 v0 = make_float2(acc[mt][nt][0], acc[mt][nt][1]);
            float2 v1 = make_float2(acc[mt][nt][2], acc[mt][nt][3]);
            if (res) {
                float2 r0v = *(const float2*)(res + o0);
                float2 r1v = *(const float2*)(res + o1);
                v0.x += r0v.x; v0.y += r0v.y;
                v1.x += r1v.x; v1.y += r1v.y;
            }
            *(float2*)(C + o0) = v0;
            *(float2*)(C + o1) = v1;
        }
    }
}

// ======== w3 GEMM with fused SiLU: out = silu(hb) * acc, fp16 ========
__global__ __launch_bounds__(256, 2) void gemmw3silu_k(
    const __half* __restrict__ Ah, const __half* __restrict__ Bh,
    const float* __restrict__ hb, __half* __restrict__ outh, int N, int K)
{
    GEMM_PREAMBLE();
    GEMM_MAIN();

    const int gid = lane >> 2, t4 = lane & 3;
    #pragma unroll
    for (int mt = 0; mt < 4; mt++) {
        int r0 = bm + wm * 64 + mt * 16 + gid;
        #pragma unroll
        for (int nt = 0; nt < 4; nt++) {
            int col = bn + wn * 32 + nt * 8 + t4 * 2;
            size_t o0 = (size_t)r0 * N + col;
            size_t o1 = o0 + (size_t)8 * N;
            float2 h0 = *(const float2*)(hb + o0);
            float2 h1 = *(const float2*)(hb + o1);
            float y0 = acc[mt][nt][0] * h0.x / (1.f + __expf(-h0.x));
            float y1 = acc[mt][nt][1] * h0.y / (1.f + __expf(-h0.y));
            float y2 = acc[mt][nt][2] * h1.x / (1.f + __expf(-h1.x));
            float y3 = acc[mt][nt][3] * h1.y / (1.f + __expf(-h1.y));
            *(__half2*)(outh + o0) = __floats2half2_rn(y0, y1);
            *(__half2*)(outh + o1) = __floats2half2_rn(y2, y3);
        }
    }
}

// ======== QKV GEMM with fused RoPE + head-major fp16 output ========
__global__ __launch_bounds__(256, 2) void gemmqkv_k(
    const __half* __restrict__ Ah, const __half* __restrict__ Bh,
    const float* __restrict__ rt,
    __half* __restrict__ qhb, __half* __restrict__ khb,
    __half* __restrict__ vhb)
{
    const int K = DM;
    GEMM_PREAMBLE();
    GEMM_MAIN();

    const int gid = lane >> 2, t4 = lane & 3;
    #pragma unroll
    for (int mt = 0; mt < 4; mt++) {
        int r0 = bm + wm * 64 + mt * 16 + gid;
        #pragma unroll
        for (int nt = 0; nt < 4; nt++) {
            int col = bn + wn * 32 + nt * 8 + t4 * 2;
            int t   = col >> 10;
            int rem = col & 1023;
            int hh  = rem >> 6;
            int d   = rem & 63;
            int p   = d >> 1;
            __half* dstbuf = (t == 0) ? qhb : (t == 1) ? khb : vhb;
            #pragma unroll
            for (int half_ = 0; half_ < 2; half_++) {
                int r = r0 + half_ * 8;
                float v0 = acc[mt][nt][half_ * 2];
                float v1 = acc[mt][nt][half_ * 2 + 1];
                int s = r & (SEQ - 1);
                int b = r >> 11;
                size_t dst = ((size_t)(b * NH + hh) * SEQ + s) * DK + d;
                if (t < 2) {
                    float2 cs = ((const float2*)rt)[s * 32 + p];
                    float x0 = cs.x * v0 - cs.y * v1;
                    float x1 = cs.y * v0 + cs.x * v1;
                    v0 = x0; v1 = x1;
                }
                *(__half2*)(dstbuf + dst) = __floats2half2_rn(v0, v1);
            }
        }
    }
}

// ================= fp16 HMMA flash attention (QT=64, 128 thr) =================
#define QT 64
#define LDS 72
#define NEG_BIG (-1.0e30f)

__global__ __launch_bounds__(128) void flashm_k(const __half* __restrict__ qhb,
                                                const __half* __restrict__ khb,
                                                const __half* __restrict__ vhb,
                                                __half* __restrict__ ah)
{
    __shared__ __align__(128) __half Qs[QT * LDS];
    __shared__ __align__(128) __half Ks[2][64 * LDS];
    __shared__ __align__(128) __half Vs[2][64 * LDS];

    const int tid  = threadIdx.x;
    const int lane = tid & 31;
    const int w    = tid >> 5;
    const int bh   = blockIdx.y;
    const int b    = bh >> 4, h = bh & 15;
    const int qt   = gridDim.x - 1 - blockIdx.x;
    const int qbase = qt * QT;

    const uint32_t qs = smem_u32(Qs);
    const uint32_t ks0 = smem_u32(Ks);
    const uint32_t vs0 = smem_u32(Vs);

    const __half* qg = qhb + ((size_t)bh * SEQ + qbase) * DK;
    #pragma unroll
    for (int i = 0; i < 4; i++) {
        int slot = tid + (i << 7);
        int r = slot >> 3, c8 = (slot & 7) << 3;
        cpa16(qs + (uint32_t)(r * LDS + c8) * 2, qg + r * 64 + c8);
    }
    CP_COMMIT();

    const __half* kg = khb + (size_t)bh * SEQ * DK;
    const __half* vg = vhb + (size_t)bh * SEQ * DK;

    #define FKV_LOAD(t, buf) do {                                              \
        int n0_ = (t) * 64;                                                    \
        _Pragma("unroll")                                                      \
        for (int i_ = 0; i_ < 4; i_++) {                                       \
            int slot_ = tid + (i_ << 7);                                       \
            int r_ = slot_ >> 3, c8_ = (slot_ & 7) << 3;                       \
            uint32_t so_ = (uint32_t)((buf) * 64 * LDS + r_ * LDS + c8_) * 2;  \
            cpa16(ks0 + so_, kg + (size_t)(n0_ + r_) * 64 + c8_);              \
            cpa16(vs0 + so_, vg + (size_t)(n0_ + r_) * 64 + c8_);              \
        }                                                                      \
        CP_COMMIT();                                                           \
    } while (0)

    const int T = qt + 1;
    FKV_LOAD(0, 0);

    const int gid = lane >> 2, t4 = lane & 3;
    const int qg0 = qbase + w * 16 + gid;

    uint32_t aQ[4][4];
    float oacc[8][4];
    #pragma unroll
    for (int i = 0; i < 8; i++)
        #pragma unroll
        for (int j = 0; j < 4; j++) oacc[i][j] = 0.f;
    float m0 = NEG_BIG, m1 = NEG_BIG, l0 = 0.f, l1 = 0.f;

    const int arow = lane & 15;
    const int acolo = (lane >> 4) << 3;
    const int bro = lane & 7;
    const int bcolo = ((lane >> 3) & 1) << 3;
    const int l15 = lane & 15;

    for (int t = 0; t < T; t++) {
        const int buf = t & 1;
        if (t + 1 < T) { FKV_LOAD(t + 1, buf ^ 1); CP_WAIT1(); }
        else           { CP_WAIT0(); }
        __syncthreads();

        if (t == 0) {
            #pragma unroll
            for (int k = 0; k < 4; k++) {
                uint32_t ad = qs + (uint32_t)((w * 16 + arow) * LDS + k * 16 + acolo) * 2;
                ldm_x4(aQ[k], ad);
            }
        }

        const uint32_t kb = ks0 + (uint32_t)(buf * 64 * LDS) * 2;
        const uint32_t vb = vs0 + (uint32_t)(buf * 64 * LDS) * 2;
        const int n0 = t * 64;

        float sacc[8][4];
        #pragma unroll
        for (int i = 0; i < 8; i++)
            #pragma unroll
            for (int j = 0; j < 4; j++) sacc[i][j] = 0.f;

        #pragma unroll
        for (int k = 0; k < 4; k++) {
            #pragma unroll
            for (int nt = 0; nt < 8; nt++) {
                uint32_t bk[2];
                uint32_t bd = kb + (uint32_t)((nt * 8 + bro) * LDS + k * 16 + bcolo) * 2;
                ldm_x2(bk, bd);
                MMAH(sacc[nt], aQ[k], bk);
            }
        }

        const bool diag = (t == qt);
        #pragma unroll
        for (int nt = 0; nt < 8; nt++) {
            int kvb = n0 + nt * 8 + t4 * 2;
            #pragma unroll
            for (int c = 0; c < 2; c++) {
                float s0 = sacc[nt][c]   * 0.125f;
                float s1 = sacc[nt][c+2] * 0.125f;
                if (diag) {
                    if (kvb + c > qg0)     s0 = NEG_BIG;
                    if (kvb + c > qg0 + 8) s1 = NEG_BIG;
                }
                sacc[nt][c]   = s0;
                sacc[nt][c+2] = s1;
            }
        }

        float vmax0 = NEG_BIG, vmax1 = NEG_BIG;
        #pragma unroll
        for (int nt = 0; nt < 8; nt++) {
            vmax0 = fmaxf(vmax0, fmaxf(sacc[nt][0], sacc[nt][1]));
            vmax1 = fmaxf(vmax1, fmaxf(sacc[nt][2], sacc[nt][3]));
        }
        vmax0 = fmaxf(vmax0, __shfl_xor_sync(0xffffffffu, vmax0, 1));
        vmax0 = fmaxf(vmax0, __shfl_xor_sync(0xffffffffu, vmax0, 2));
        vmax1 = fmaxf(vmax1, __shfl_xor_sync(0xffffffffu, vmax1, 1));
        vmax1 = fmaxf(vmax1, __shfl_xor_sync(0xffffffffu, vmax1, 2));

        float mn0 = fmaxf(m0, vmax0), mn1 = fmaxf(m1, vmax1);
        float corr0 = __expf(m0 - mn0), corr1 = __expf(m1 - mn1);
        m0 = mn0; m1 = mn1;

        float lsum0 = 0.f, lsum1 = 0.f;
        #pragma unroll
        for (int nt = 0; nt < 8; nt++) {
            float p0 = __expf(sacc[nt][0] - mn0);
            float p1 = __expf(sacc[nt][1] - mn0);
            float p2 = __expf(sacc[nt][2] - mn1);
            float p3 = __expf(sacc[nt][3] - mn1);
            sacc[nt][0] = p0; sacc[nt][1] = p1; sacc[nt][2] = p2; sacc[nt][3] = p3;
            lsum0 += p0 + p1; lsum1 += p2 + p3;
        }
        lsum0 += __shfl_xor_sync(0xffffffffu, lsum0, 1);
        lsum0 += __shfl_xor_sync(0xffffffffu, lsum0, 2);
        lsum1 += __shfl_xor_sync(0xffffffffu, lsum1, 1);
        lsum1 += __shfl_xor_sync(0xffffffffu, lsum1, 2);
        l0 = l0 * corr0 + lsum0;
        l1 = l1 * corr1 + lsum1;

        #pragma unroll
        for (int nt = 0; nt < 8; nt++) {
            oacc[nt][0] *= corr0; oacc[nt][1] *= corr0;
            oacc[nt][2] *= corr1; oacc[nt][3] *= corr1;
        }

        #pragma unroll
        for (int kp = 0; kp < 4; kp++) {
            uint32_t pa[4];
            pa[0] = packh(sacc[2*kp][0],   sacc[2*kp][1]);
            pa[1] = packh(sacc[2*kp][2],   sacc[2*kp][3]);
            pa[2] = packh(sacc[2*kp+1][0], sacc[2*kp+1][1]);
            pa[3] = packh(sacc[2*kp+1][2], sacc[2*kp+1][3]);
            #pragma unroll
            for (int ntd = 0; ntd < 8; ntd++) {
                uint32_t bv[2];
                uint32_t vd = vb + (uint32_t)((kp * 16 + l15) * LDS + ntd * 8) * 2;
                ldm_x2t(bv, vd);
                MMAH(oacc[ntd], pa, bv);
            }
        }
        __syncthreads();
    }

    float invl0 = 1.f / l0, invl1 = 1.f / l1;
    const size_t row0 = (size_t)(b * SEQ + qbase + w * 16 + gid);
    #pragma unroll
    for (int ntd = 0; ntd < 8; ntd++) {
        int col = h * 64 + ntd * 8 + t4 * 2;
        *(__half2*)(ah + row0 * DM + col) =
            __floats2half2_rn(oacc[ntd][0] * invl0, oacc[ntd][1] * invl0);
        *(__half2*)(ah + (row0 + 8) * DM + col) =
            __floats2half2_rn(oacc[ntd][2] * invl1, oacc[ntd][3] * invl1);
    }
}

// ================= launch =================
extern "C" void kernel_launch(void* const* d_in, const int* in_sizes, int n_in,
                              void* d_out, int out_size)
{
    const float* x      = (const float*)d_in[0];
    const float* qkv_w  = (const float*)d_in[2];
    const float* o_w    = (const float*)d_in[3];
    const float* gain1  = (const float*)d_in[4];
    const float* gain2  = (const float*)d_in[5];
    const float* w1     = (const float*)d_in[6];
    const float* w2     = (const float*)d_in[7];
    const float* w3     = (const float*)d_in[8];
    float* out = (float*)d_out;

    float *h1, *hb, *gb, *rt, *xn;
    __half *ah, *wh;
    cudaGetSymbolAddress((void**)&h1,  g_h1);
    cudaGetSymbolAddress((void**)&xn,  g_xn);
    cudaGetSymbolAddress((void**)&hb,  g_h);
    cudaGetSymbolAddress((void**)&gb,  g_g);
    cudaGetSymbolAddress((void**)&rt,  g_rt);
    cudaGetSymbolAddress((void**)&ah,  g_ah);
    cudaGetSymbolAddress((void**)&wh,  g_wh);

    __half* qhb = (__half*)xn;
    __half* khb = (__half*)xn + (size_t)MROWS*DM;
    __half* vhb = (__half*)hb;
    __half* sgh = (__half*)gb;      // silu-product fp16

    cudaFuncSetAttribute(gemmh_k,      cudaFuncAttributeMaxDynamicSharedMemorySize, SMEMB);
    cudaFuncSetAttribute(gemmqkv_k,    cudaFuncAttributeMaxDynamicSharedMemorySize, SMEMB);
    cudaFuncSetAttribute(gemmw3silu_k, cudaFuncAttributeMaxDynamicSharedMemorySize, SMEMB);

    ropetab_k<<<(SEQ*32 + 255)/256, 256>>>(rt);
    conv_pad_k<<<(3145728/4 + 255)/256, 256>>>(qkv_w, wh+OQKV, 3072,1024,3072,1024);
    rmsnorm_h_k<<<MROWS, 256>>>(x, gain1, ah);
    gemmqkv_k<<<dim3(3072/128, MROWS/128), 256, SMEMB>>>(ah, wh+OQKV, rt, qhb, khb, vhb);
    flashm_k<<<dim3(SEQ/QT, BATCH*NH), 128>>>(qhb, khb, vhb, ah);
    conv_pad_k<<<(1048576/4 + 255)/256, 256>>>(o_w, wh+OO, 1024,1024,1024,1024);
    gemmh_k<<<dim3(DM/128, MROWS/128), 256, SMEMB>>>(ah, wh+OO, h1, x, DM, DM);
    rmsnorm_h_k<<<MROWS, 256>>>(h1, gain2, ah);
    conv_pad_k<<<((DFP*1024)/4 + 255)/256, 256>>>(w1, wh+OW1, DFF,1024,DFP,1024);
    conv_pad_k<<<((DFP*1024)/4 + 255)/256, 256>>>(w3, wh+OW3, DFF,1024,DFP,1024);
    gemmh_k<<<dim3(DFP/128, MROWS/128), 256, SMEMB>>>(ah, wh+OW1, hb, nullptr, DFP, DM);
    gemmw3silu_k<<<dim3(DFP/128, MROWS/128), 256, SMEMB>>>(ah, wh+OW3, hb, sgh, DFP, DM);
    conv_pad_k<<<((1024*DFP)/4 + 255)/256, 256>>>(w2, wh+OW2, 1024,DFF,1024,DFP);
    gemmh_k<<<dim3(DM/128, MROWS/128), 256, SMEMB>>>(sgh, wh+OW2, out, h1, DM, DFP);
}